// round 4
// baseline (speedup 1.0000x reference)
#include <cuda_runtime.h>

#define N_NODES 100000
#define N_EDGES 1600000
#define N_GRAPHS 2000
#define HID 128
#define BN_EPS 1e-5f

// ---------------- scratch (device globals; no allocation allowed) ----------------
__device__ float g_y[N_NODES * HID];      // y = (h @ W) * norm     (51.2 MB)
__device__ float g_h[N_NODES * HID];      // activations            (51.2 MB)
__device__ float g_norm[N_NODES];
__device__ int   g_deg[N_NODES];
__device__ int   g_rowptr[N_NODES + 1];
__device__ int   g_cursor[N_NODES];
__device__ int   g_srcs[N_EDGES];         // CSR by dst (6.4 MB)
__device__ float g_pool[N_GRAPHS * HID];
__device__ float g_cnt[N_GRAPHS];

// ---------------- setup kernels ----------------
__global__ void init_kernel() {
    int i = blockIdx.x * blockDim.x + threadIdx.x;
    int stride = gridDim.x * blockDim.x;
    for (int t = i; t < N_GRAPHS * HID; t += stride) g_pool[t] = 0.f;
    for (int t = i; t < N_NODES; t += stride) g_deg[t] = 0;
    for (int t = i; t < N_GRAPHS; t += stride) g_cnt[t] = 0.f;
}

__global__ void count_kernel(const int* __restrict__ dst) {
    int e = blockIdx.x * blockDim.x + threadIdx.x;
    if (e < N_EDGES) atomicAdd(&g_deg[dst[e]], 1);
}

// Single-block scan over degrees -> rowptr/cursor, plus norm = rsqrt(deg+1).
__global__ void prefix_kernel() {
    __shared__ int warp_sums[32];
    __shared__ int s_carry;
    int tid = threadIdx.x;
    int lane = tid & 31, wid = tid >> 5;
    if (tid == 0) s_carry = 0;
    __syncthreads();
    for (int base = 0; base < N_NODES; base += 1024) {
        int idx = base + tid;
        int v = (idx < N_NODES) ? g_deg[idx] : 0;
        int x = v;
        #pragma unroll
        for (int o = 1; o < 32; o <<= 1) {
            int t = __shfl_up_sync(0xFFFFFFFFu, x, o);
            if (lane >= o) x += t;
        }
        if (lane == 31) warp_sums[wid] = x;
        __syncthreads();
        if (wid == 0) {
            int ws = warp_sums[lane];
            #pragma unroll
            for (int o = 1; o < 32; o <<= 1) {
                int t = __shfl_up_sync(0xFFFFFFFFu, ws, o);
                if (lane >= o) ws += t;
            }
            warp_sums[lane] = ws;
        }
        __syncthreads();
        int warp_off = (wid > 0) ? warp_sums[wid - 1] : 0;
        int incl = x + warp_off;
        int carry = s_carry;
        if (idx < N_NODES) {
            int excl = carry + incl - v;
            g_rowptr[idx] = excl;
            g_cursor[idx] = excl;
            g_norm[idx] = rsqrtf((float)v + 1.0f);
        }
        __syncthreads();
        if (tid == 1023) s_carry = carry + incl;
        __syncthreads();
    }
    if (tid == 0) g_rowptr[N_NODES] = s_carry;
}

__global__ void scatter_kernel(const int* __restrict__ src, const int* __restrict__ dst) {
    int e = blockIdx.x * blockDim.x + threadIdx.x;
    if (e < N_EDGES) {
        int d = dst[e];
        int pos = atomicAdd(&g_cursor[d], 1);
        g_srcs[pos] = src[e];
    }
}

// ---------------- GEMM: y = (hin @ W) * norm ----------------
// 64x128 tile, K=128 chunked by 32. 256 threads, 4x8 micro-tile per thread.
__global__ __launch_bounds__(256) void gemm_kernel(const float* __restrict__ x,
                                                   const float* __restrict__ W,
                                                   int first) {
    const float* __restrict__ hin = first ? x : g_h;
    __shared__ float As[64][33];
    __shared__ float Bs[32][128];
    int tid = threadIdx.x;
    int tx = tid & 15, ty = tid >> 4;
    int m0 = blockIdx.x * 64;

    float acc[4][8];
    #pragma unroll
    for (int i = 0; i < 4; i++)
        #pragma unroll
        for (int j = 0; j < 8; j++) acc[i][j] = 0.f;

    for (int k0 = 0; k0 < HID; k0 += 32) {
        #pragma unroll
        for (int t = tid; t < 512; t += 256) {   // 64 rows x 8 float4
            int r = t >> 3, c4 = (t & 7) << 2;
            int row = m0 + r;
            float4 v = make_float4(0.f, 0.f, 0.f, 0.f);
            if (row < N_NODES)
                v = *reinterpret_cast<const float4*>(hin + row * HID + k0 + c4);
            As[r][c4] = v.x; As[r][c4 + 1] = v.y; As[r][c4 + 2] = v.z; As[r][c4 + 3] = v.w;
        }
        #pragma unroll
        for (int t = tid; t < 1024; t += 256) {  // 32 rows x 32 float4
            int r = t >> 5, c4 = (t & 31) << 2;
            *reinterpret_cast<float4*>(&Bs[r][c4]) =
                *reinterpret_cast<const float4*>(W + (k0 + r) * HID + c4);
        }
        __syncthreads();
        #pragma unroll
        for (int kk = 0; kk < 32; kk++) {
            float a[4], b[8];
            #pragma unroll
            for (int i = 0; i < 4; i++) a[i] = As[ty * 4 + i][kk];
            #pragma unroll
            for (int j = 0; j < 8; j++) b[j] = Bs[kk][tx + j * 16];
            #pragma unroll
            for (int i = 0; i < 4; i++)
                #pragma unroll
                for (int j = 0; j < 8; j++) acc[i][j] += a[i] * b[j];
        }
        __syncthreads();
    }
    #pragma unroll
    for (int i = 0; i < 4; i++) {
        int row = m0 + ty * 4 + i;
        if (row < N_NODES) {
            float nrm = g_norm[row];
            #pragma unroll
            for (int j = 0; j < 8; j++)
                g_y[row * HID + tx + j * 16] = acc[i][j] * nrm;
        }
    }
}

// ---------------- aggregation + BN(eval) + ReLU, warp per node ----------------
__global__ __launch_bounds__(256) void agg_kernel(const float* __restrict__ bs,
                                                  const float* __restrict__ gam,
                                                  const float* __restrict__ bet,
                                                  const float* __restrict__ mean,
                                                  const float* __restrict__ var) {
    int wid = threadIdx.x >> 5, lane = threadIdx.x & 31;
    int n = blockIdx.x * 8 + wid;
    if (n >= N_NODES) return;
    const float4* __restrict__ y4 = reinterpret_cast<const float4*>(g_y);

    float4 acc = y4[n * 32 + lane];            // self term: norm^2*xw = norm*y[n]
    int e0 = g_rowptr[n], e1 = g_rowptr[n + 1];
    for (int e = e0; e < e1; e++) {
        int s = g_srcs[e];
        float4 v = y4[s * 32 + lane];
        acc.x += v.x; acc.y += v.y; acc.z += v.z; acc.w += v.w;
    }
    float nrm = g_norm[n];
    int j = lane * 4;
    float4 b4 = *reinterpret_cast<const float4*>(bs + j);
    float4 g4 = *reinterpret_cast<const float4*>(gam + j);
    float4 be4 = *reinterpret_cast<const float4*>(bet + j);
    float4 m4 = *reinterpret_cast<const float4*>(mean + j);
    float4 v4 = *reinterpret_cast<const float4*>(var + j);
    float4 r;
    r.x = fmaxf((nrm * acc.x + b4.x - m4.x) * (g4.x * rsqrtf(v4.x + BN_EPS)) + be4.x, 0.f);
    r.y = fmaxf((nrm * acc.y + b4.y - m4.y) * (g4.y * rsqrtf(v4.y + BN_EPS)) + be4.y, 0.f);
    r.z = fmaxf((nrm * acc.z + b4.z - m4.z) * (g4.z * rsqrtf(v4.z + BN_EPS)) + be4.z, 0.f);
    r.w = fmaxf((nrm * acc.w + b4.w - m4.w) * (g4.w * rsqrtf(v4.w + BN_EPS)) + be4.w, 0.f);
    reinterpret_cast<float4*>(g_h)[n * 32 + lane] = r;
}

// ---------------- pooling ----------------
__global__ __launch_bounds__(256) void pool_kernel(const int* __restrict__ batch) {
    int wid = threadIdx.x >> 5, lane = threadIdx.x & 31;
    int n = blockIdx.x * 8 + wid;
    if (n >= N_NODES) return;
    int b = batch[n];
    float4 v = reinterpret_cast<const float4*>(g_h)[n * 32 + lane];
    float* p = &g_pool[b * HID + lane * 4];
    atomicAdd(p, v.x); atomicAdd(p + 1, v.y); atomicAdd(p + 2, v.z); atomicAdd(p + 3, v.w);
    if (lane == 0) atomicAdd(&g_cnt[b], 1.0f);
}

// ---------------- final projection: out[g] = pooled[g] @ W_out + b_out ----------------
__global__ __launch_bounds__(128) void out_kernel(const float* __restrict__ W_out,
                                                  const float* __restrict__ b_out,
                                                  float* __restrict__ out) {
    int g = blockIdx.x;
    int tid = threadIdx.x;
    int lane = tid & 31, wid = tid >> 5;
    float cnt = fmaxf(g_cnt[g], 1.0f);
    float p = g_pool[g * HID + tid] / cnt;
    float v[5];
    #pragma unroll
    for (int o = 0; o < 5; o++) v[o] = p * W_out[tid * 5 + o];
    #pragma unroll
    for (int o = 0; o < 5; o++)
        #pragma unroll
        for (int off = 16; off > 0; off >>= 1)
            v[o] += __shfl_down_sync(0xFFFFFFFFu, v[o], off);
    __shared__ float sred[4][5];
    if (lane == 0) {
        #pragma unroll
        for (int o = 0; o < 5; o++) sred[wid][o] = v[o];
    }
    __syncthreads();
    if (tid < 5) {
        float s = sred[0][tid] + sred[1][tid] + sred[2][tid] + sred[3][tid] + b_out[tid];
        out[g * 5 + tid] = s;
    }
}

// ---------------- launch ----------------
extern "C" void kernel_launch(void* const* d_in, const int* in_sizes, int n_in,
                              void* d_out, int out_size) {
    const float* x      = (const float*)d_in[0];
    const int*   edge   = (const int*)d_in[1];
    const int*   batch  = (const int*)d_in[2];
    const float* Ws     = (const float*)d_in[3];
    const float* bs     = (const float*)d_in[4];
    const float* gammas = (const float*)d_in[5];
    const float* betas  = (const float*)d_in[6];
    const float* rmean  = (const float*)d_in[7];
    const float* rvar   = (const float*)d_in[8];
    const float* W_out  = (const float*)d_in[9];
    const float* b_out  = (const float*)d_in[10];
    const int* src = edge;
    const int* dst = edge + N_EDGES;

    init_kernel<<<256, 256>>>();
    count_kernel<<<(N_EDGES + 255) / 256, 256>>>(dst);
    prefix_kernel<<<1, 1024>>>();
    scatter_kernel<<<(N_EDGES + 255) / 256, 256>>>(src, dst);

    int gemm_blocks = (N_NODES + 63) / 64;
    int node_warp_blocks = (N_NODES + 7) / 8;
    for (int l = 0; l < 4; l++) {
        gemm_kernel<<<gemm_blocks, 256>>>(x, Ws + l * HID * HID, l == 0 ? 1 : 0);
        agg_kernel<<<node_warp_blocks, 256>>>(bs + l * HID, gammas + l * HID,
                                              betas + l * HID, rmean + l * HID,
                                              rvar + l * HID);
    }
    pool_kernel<<<node_warp_blocks, 256>>>(batch);
    out_kernel<<<N_GRAPHS, 128>>>(W_out, b_out, (float*)d_out);
}

// round 5
// speedup vs baseline: 1.1125x; 1.1125x over previous
#include <cuda_runtime.h>
#include <cstdint>

#define N_NODES 100000
#define N_EDGES 1600000
#define N_GRAPHS 2000
#define HID 128
#define BN_EPS 1e-5f

// ---------------- scratch (device globals; no allocation allowed) ----------------
__device__ float g_y[N_NODES * HID];      // y = (h @ W) * norm     (51.2 MB)
__device__ float g_h[N_NODES * HID];      // activations            (51.2 MB)
__device__ float g_norm[N_NODES];
__device__ int   g_deg[N_NODES];
__device__ int   g_rowptr[N_NODES + 1];
__device__ int   g_cursor[N_NODES];
__device__ int   g_srcs[N_EDGES];         // CSR by dst (6.4 MB)
__device__ float g_pool[N_GRAPHS * HID];
__device__ float g_cnt[N_GRAPHS];

// ---------------- setup kernels ----------------
__global__ void init_kernel() {
    int i = blockIdx.x * blockDim.x + threadIdx.x;
    int stride = gridDim.x * blockDim.x;
    for (int t = i; t < N_GRAPHS * HID; t += stride) g_pool[t] = 0.f;
    for (int t = i; t < N_NODES; t += stride) g_deg[t] = 0;
    for (int t = i; t < N_GRAPHS; t += stride) g_cnt[t] = 0.f;
}

__global__ void count_kernel(const int* __restrict__ dst) {
    int e = blockIdx.x * blockDim.x + threadIdx.x;
    if (e < N_EDGES) atomicAdd(&g_deg[dst[e]], 1);
}

// Single-block scan over degrees -> rowptr/cursor, plus norm = rsqrt(deg+1).
__global__ void prefix_kernel() {
    __shared__ int warp_sums[32];
    __shared__ int s_carry;
    int tid = threadIdx.x;
    int lane = tid & 31, wid = tid >> 5;
    if (tid == 0) s_carry = 0;
    __syncthreads();
    for (int base = 0; base < N_NODES; base += 1024) {
        int idx = base + tid;
        int v = (idx < N_NODES) ? g_deg[idx] : 0;
        int x = v;
        #pragma unroll
        for (int o = 1; o < 32; o <<= 1) {
            int t = __shfl_up_sync(0xFFFFFFFFu, x, o);
            if (lane >= o) x += t;
        }
        if (lane == 31) warp_sums[wid] = x;
        __syncthreads();
        if (wid == 0) {
            int ws = warp_sums[lane];
            #pragma unroll
            for (int o = 1; o < 32; o <<= 1) {
                int t = __shfl_up_sync(0xFFFFFFFFu, ws, o);
                if (lane >= o) ws += t;
            }
            warp_sums[lane] = ws;
        }
        __syncthreads();
        int warp_off = (wid > 0) ? warp_sums[wid - 1] : 0;
        int incl = x + warp_off;
        int carry = s_carry;
        if (idx < N_NODES) {
            int excl = carry + incl - v;
            g_rowptr[idx] = excl;
            g_cursor[idx] = excl;
            g_norm[idx] = rsqrtf((float)v + 1.0f);
        }
        __syncthreads();
        if (tid == 1023) s_carry = carry + incl;
        __syncthreads();
    }
    if (tid == 0) g_rowptr[N_NODES] = s_carry;
}

__global__ void scatter_kernel(const int* __restrict__ src, const int* __restrict__ dst) {
    int e = blockIdx.x * blockDim.x + threadIdx.x;
    if (e < N_EDGES) {
        int d = dst[e];
        int pos = atomicAdd(&g_cursor[d], 1);
        g_srcs[pos] = src[e];
    }
}

// ---------------- split-TF32 tensor-core GEMM: y = (hin @ W) * norm ----------------
// Block tile 128x128, K=128 in a single smem shot.
// 8 warps (4 M x 2 N), warp tile 32x64 via m16n8k8 tf32 mma.
// Error-compensated: a*b ~= ahi*bhi + ahi*blo + alo*bhi (fp32-class accuracy).

#define LDA 132   // banks for A frag loads: (4*gr + gc) % 32 -> bijective
#define LDB 136   // banks for B frag loads: (8*gc + gr) % 32 -> bijective
#define GEMM_SMEM ((128 * LDA + 128 * LDB) * 4)

__device__ __forceinline__ uint32_t f2tf32(float f) {
    uint32_t r;
    asm("cvt.rna.tf32.f32 %0, %1;" : "=r"(r) : "f"(f));
    return r;
}
__device__ __forceinline__ void split_tf32(float f, uint32_t& hi, uint32_t& lo) {
    hi = f2tf32(f);
    float rem = f - __uint_as_float(hi);
    lo = f2tf32(rem);
}
__device__ __forceinline__ void mma_tf32(float4& d, const uint32_t* a, const uint32_t* b) {
    asm volatile(
        "mma.sync.aligned.m16n8k8.row.col.f32.tf32.tf32.f32 "
        "{%0,%1,%2,%3}, {%4,%5,%6,%7}, {%8,%9}, {%0,%1,%2,%3};"
        : "+f"(d.x), "+f"(d.y), "+f"(d.z), "+f"(d.w)
        : "r"(a[0]), "r"(a[1]), "r"(a[2]), "r"(a[3]), "r"(b[0]), "r"(b[1]));
}

__global__ __launch_bounds__(256) void gemm_tf32_kernel(const float* __restrict__ x,
                                                        const float* __restrict__ W,
                                                        int first) {
    const float* __restrict__ hin = first ? x : g_h;
    extern __shared__ float smem[];
    float* As = smem;               // [128][LDA]
    float* Bs = smem + 128 * LDA;   // [128][LDB]
    int tid = threadIdx.x;
    int m0 = blockIdx.x * 128;

    // stage A tile (zero-pad OOB rows)
    #pragma unroll
    for (int i = 0; i < 16; i++) {
        int linear = tid + i * 256;          // 4096 float4 slots
        int row = linear >> 5;
        int c4 = (linear & 31) << 2;
        float4 v = make_float4(0.f, 0.f, 0.f, 0.f);
        if (m0 + row < N_NODES)
            v = *reinterpret_cast<const float4*>(hin + (size_t)(m0 + row) * HID + c4);
        float* p = As + row * LDA + c4;
        p[0] = v.x; p[1] = v.y; p[2] = v.z; p[3] = v.w;
    }
    // stage W
    #pragma unroll
    for (int i = 0; i < 16; i++) {
        int linear = tid + i * 256;
        int row = linear >> 5;
        int c4 = (linear & 31) << 2;
        float4 v = *reinterpret_cast<const float4*>(W + row * HID + c4);
        float* p = Bs + row * LDB + c4;
        p[0] = v.x; p[1] = v.y; p[2] = v.z; p[3] = v.w;
    }
    __syncthreads();

    int lane = tid & 31, wid = tid >> 5;
    int warpM = wid >> 1, warpN = wid & 1;
    int mbase = warpM * 32, nbase = warpN * 64;
    int gr = lane >> 2, gc = lane & 3;

    float4 acc[2][8];
    #pragma unroll
    for (int mf = 0; mf < 2; mf++)
        #pragma unroll
        for (int nf = 0; nf < 8; nf++)
            acc[mf][nf] = make_float4(0.f, 0.f, 0.f, 0.f);

    #pragma unroll
    for (int ks = 0; ks < 16; ks++) {
        int k0 = ks * 8;
        uint32_t ahi[2][4], alo[2][4];
        #pragma unroll
        for (int mf = 0; mf < 2; mf++) {
            int r = mbase + mf * 16 + gr;
            float f0 = As[r * LDA + k0 + gc];
            float f1 = As[(r + 8) * LDA + k0 + gc];
            float f2 = As[r * LDA + k0 + gc + 4];
            float f3 = As[(r + 8) * LDA + k0 + gc + 4];
            split_tf32(f0, ahi[mf][0], alo[mf][0]);
            split_tf32(f1, ahi[mf][1], alo[mf][1]);
            split_tf32(f2, ahi[mf][2], alo[mf][2]);
            split_tf32(f3, ahi[mf][3], alo[mf][3]);
        }
        uint32_t bhi[8][2], blo[8][2];
        #pragma unroll
        for (int nf = 0; nf < 8; nf++) {
            int c = nbase + nf * 8 + gr;
            float f0 = Bs[(k0 + gc) * LDB + c];
            float f1 = Bs[(k0 + 4 + gc) * LDB + c];
            split_tf32(f0, bhi[nf][0], blo[nf][0]);
            split_tf32(f1, bhi[nf][1], blo[nf][1]);
        }
        #pragma unroll
        for (int mf = 0; mf < 2; mf++)
            #pragma unroll
            for (int nf = 0; nf < 8; nf++) {
                mma_tf32(acc[mf][nf], ahi[mf], bhi[nf]);
                mma_tf32(acc[mf][nf], ahi[mf], blo[nf]);
                mma_tf32(acc[mf][nf], alo[mf], bhi[nf]);
            }
    }

    // epilogue: y = acc * norm[row]
    #pragma unroll
    for (int mf = 0; mf < 2; mf++) {
        int r0 = m0 + mbase + mf * 16 + gr;
        int r1 = r0 + 8;
        float n0 = (r0 < N_NODES) ? g_norm[r0] : 0.f;
        float n1 = (r1 < N_NODES) ? g_norm[r1] : 0.f;
        #pragma unroll
        for (int nf = 0; nf < 8; nf++) {
            int c = nbase + nf * 8 + gc * 2;
            if (r0 < N_NODES) {
                float2 v = make_float2(acc[mf][nf].x * n0, acc[mf][nf].y * n0);
                *reinterpret_cast<float2*>(g_y + (size_t)r0 * HID + c) = v;
            }
            if (r1 < N_NODES) {
                float2 v = make_float2(acc[mf][nf].z * n1, acc[mf][nf].w * n1);
                *reinterpret_cast<float2*>(g_y + (size_t)r1 * HID + c) = v;
            }
        }
    }
}

// ---------------- aggregation + BN(eval) + ReLU, warp per node ----------------
// last!=0: fuse global-mean-pool (atomicAdd into g_pool) instead of writing g_h.
__global__ __launch_bounds__(256) void agg_kernel(const float* __restrict__ bs,
                                                  const float* __restrict__ gam,
                                                  const float* __restrict__ bet,
                                                  const float* __restrict__ mean,
                                                  const float* __restrict__ var,
                                                  const int* __restrict__ batch,
                                                  int last) {
    int wid = threadIdx.x >> 5, lane = threadIdx.x & 31;
    int n = blockIdx.x * 8 + wid;
    if (n >= N_NODES) return;
    const float4* __restrict__ y4 = reinterpret_cast<const float4*>(g_y);

    float4 acc = y4[n * 32 + lane];            // self term: norm^2*xw = norm*y[n]
    int e0 = g_rowptr[n], e1 = g_rowptr[n + 1];
    for (int e = e0; e < e1; e++) {
        int s = g_srcs[e];
        float4 v = y4[s * 32 + lane];
        acc.x += v.x; acc.y += v.y; acc.z += v.z; acc.w += v.w;
    }
    float nrm = g_norm[n];
    int j = lane * 4;
    float4 b4 = *reinterpret_cast<const float4*>(bs + j);
    float4 g4 = *reinterpret_cast<const float4*>(gam + j);
    float4 be4 = *reinterpret_cast<const float4*>(bet + j);
    float4 m4 = *reinterpret_cast<const float4*>(mean + j);
    float4 v4 = *reinterpret_cast<const float4*>(var + j);
    float4 r;
    r.x = fmaxf((nrm * acc.x + b4.x - m4.x) * (g4.x * rsqrtf(v4.x + BN_EPS)) + be4.x, 0.f);
    r.y = fmaxf((nrm * acc.y + b4.y - m4.y) * (g4.y * rsqrtf(v4.y + BN_EPS)) + be4.y, 0.f);
    r.z = fmaxf((nrm * acc.z + b4.z - m4.z) * (g4.z * rsqrtf(v4.z + BN_EPS)) + be4.z, 0.f);
    r.w = fmaxf((nrm * acc.w + b4.w - m4.w) * (g4.w * rsqrtf(v4.w + BN_EPS)) + be4.w, 0.f);
    if (!last) {
        reinterpret_cast<float4*>(g_h)[n * 32 + lane] = r;
    } else {
        int b = batch[n];
        float* p = &g_pool[b * HID + lane * 4];
        atomicAdd(p, r.x); atomicAdd(p + 1, r.y);
        atomicAdd(p + 2, r.z); atomicAdd(p + 3, r.w);
        if (lane == 0) atomicAdd(&g_cnt[b], 1.0f);
    }
}

// ---------------- final projection: out[g] = pooled[g] @ W_out + b_out ----------------
__global__ __launch_bounds__(128) void out_kernel(const float* __restrict__ W_out,
                                                  const float* __restrict__ b_out,
                                                  float* __restrict__ out) {
    int g = blockIdx.x;
    int tid = threadIdx.x;
    int lane = tid & 31, wid = tid >> 5;
    float cnt = fmaxf(g_cnt[g], 1.0f);
    float p = g_pool[g * HID + tid] / cnt;
    float v[5];
    #pragma unroll
    for (int o = 0; o < 5; o++) v[o] = p * W_out[tid * 5 + o];
    #pragma unroll
    for (int o = 0; o < 5; o++)
        #pragma unroll
        for (int off = 16; off > 0; off >>= 1)
            v[o] += __shfl_down_sync(0xFFFFFFFFu, v[o], off);
    __shared__ float sred[4][5];
    if (lane == 0) {
        #pragma unroll
        for (int o = 0; o < 5; o++) sred[wid][o] = v[o];
    }
    __syncthreads();
    if (tid < 5) {
        float s = sred[0][tid] + sred[1][tid] + sred[2][tid] + sred[3][tid] + b_out[tid];
        out[g * 5 + tid] = s;
    }
}

// ---------------- launch ----------------
extern "C" void kernel_launch(void* const* d_in, const int* in_sizes, int n_in,
                              void* d_out, int out_size) {
    const float* x      = (const float*)d_in[0];
    const int*   edge   = (const int*)d_in[1];
    const int*   batch  = (const int*)d_in[2];
    const float* Ws     = (const float*)d_in[3];
    const float* bs     = (const float*)d_in[4];
    const float* gammas = (const float*)d_in[5];
    const float* betas  = (const float*)d_in[6];
    const float* rmean  = (const float*)d_in[7];
    const float* rvar   = (const float*)d_in[8];
    const float* W_out  = (const float*)d_in[9];
    const float* b_out  = (const float*)d_in[10];
    const int* src = edge;
    const int* dst = edge + N_EDGES;

    cudaFuncSetAttribute(gemm_tf32_kernel,
                         cudaFuncAttributeMaxDynamicSharedMemorySize, GEMM_SMEM);

    init_kernel<<<256, 256>>>();
    count_kernel<<<(N_EDGES + 255) / 256, 256>>>(dst);
    prefix_kernel<<<1, 1024>>>();
    scatter_kernel<<<(N_EDGES + 255) / 256, 256>>>(src, dst);

    int gemm_blocks = (N_NODES + 127) / 128;
    int node_warp_blocks = (N_NODES + 7) / 8;
    for (int l = 0; l < 4; l++) {
        gemm_tf32_kernel<<<gemm_blocks, 256, GEMM_SMEM>>>(x, Ws + l * HID * HID,
                                                          l == 0 ? 1 : 0);
        agg_kernel<<<node_warp_blocks, 256>>>(bs + l * HID, gammas + l * HID,
                                              betas + l * HID, rmean + l * HID,
                                              rvar + l * HID, batch,
                                              l == 3 ? 1 : 0);
    }
    out_kernel<<<N_GRAPHS, 128>>>(W_out, b_out, (float*)d_out);
}

// round 6
// speedup vs baseline: 1.1362x; 1.0213x over previous
#include <cuda_runtime.h>
#include <cstdint>

#define N_NODES 100000
#define N_EDGES 1600000
#define N_GRAPHS 2000
#define HID 128
#define BN_EPS 1e-5f

// ---------------- scratch (device globals; no allocation allowed) ----------------
__device__ float g_y[N_NODES * HID];      // y = (h @ W) * norm     (51.2 MB)
__device__ float g_h[N_NODES * HID];      // activations            (51.2 MB)
__device__ float g_norm[N_NODES];
__device__ int   g_deg[N_NODES];
__device__ int   g_rowptr[N_NODES + 1];
__device__ int   g_cursor[N_NODES];
__device__ int   g_srcs[N_EDGES];         // CSR by dst (6.4 MB)
__device__ float g_pool[N_GRAPHS * HID];
__device__ float g_cnt[N_GRAPHS];

#define SCAN_BLK 4096
#define SCAN_NB ((N_NODES + SCAN_BLK - 1) / SCAN_BLK)   // 25
__device__ int g_bsum[SCAN_NB];

// ---------------- setup kernels ----------------
__global__ void init_kernel() {
    int i = blockIdx.x * blockDim.x + threadIdx.x;
    int stride = gridDim.x * blockDim.x;
    for (int t = i; t < N_GRAPHS * HID; t += stride) g_pool[t] = 0.f;
    for (int t = i; t < N_NODES; t += stride) g_deg[t] = 0;
    for (int t = i; t < N_GRAPHS; t += stride) g_cnt[t] = 0.f;
}

__global__ void count_kernel(const int* __restrict__ dst) {
    int e = blockIdx.x * blockDim.x + threadIdx.x;
    if (e < N_EDGES) atomicAdd(&g_deg[dst[e]], 1);
}

// ---- 3-phase prefix scan over g_deg -> rowptr/cursor + norm ----
__global__ __launch_bounds__(256) void scan_reduce_kernel() {
    int b = blockIdx.x;
    int base = b * SCAN_BLK;
    int tid = threadIdx.x;
    int sum = 0;
    for (int i = tid; i < SCAN_BLK; i += 256) {
        int idx = base + i;
        if (idx < N_NODES) sum += g_deg[idx];
    }
    #pragma unroll
    for (int o = 16; o > 0; o >>= 1) sum += __shfl_down_sync(0xFFFFFFFFu, sum, o);
    __shared__ int ws[8];
    int lane = tid & 31, wid = tid >> 5;
    if (lane == 0) ws[wid] = sum;
    __syncthreads();
    if (tid == 0) {
        int t = 0;
        #pragma unroll
        for (int i = 0; i < 8; i++) t += ws[i];
        g_bsum[b] = t;
    }
}

__global__ void scan_partials_kernel() {
    if (threadIdx.x == 0) {
        int acc = 0;
        #pragma unroll
        for (int i = 0; i < SCAN_NB; i++) {
            int v = g_bsum[i];
            g_bsum[i] = acc;   // exclusive
            acc += v;
        }
        g_rowptr[N_NODES] = acc;
    }
}

__global__ __launch_bounds__(1024) void scan_final_kernel() {
    int b = blockIdx.x;
    int base = b * SCAN_BLK;
    int tid = threadIdx.x;
    int lane = tid & 31, wid = tid >> 5;
    int i0 = base + tid * 4;
    int v0 = 0, v1 = 0, v2 = 0, v3 = 0;
    if (i0 + 3 < N_NODES) {
        int4 v = *reinterpret_cast<const int4*>(&g_deg[i0]);
        v0 = v.x; v1 = v.y; v2 = v.z; v3 = v.w;
    } else {
        if (i0 < N_NODES) v0 = g_deg[i0];
        if (i0 + 1 < N_NODES) v1 = g_deg[i0 + 1];
        if (i0 + 2 < N_NODES) v2 = g_deg[i0 + 2];
        if (i0 + 3 < N_NODES) v3 = g_deg[i0 + 3];
    }
    int t0 = v0, t1 = t0 + v1, t2 = t1 + v2, t3 = t2 + v3;
    int ts = t3;
    int ws_i = ts;
    #pragma unroll
    for (int o = 1; o < 32; o <<= 1) {
        int t = __shfl_up_sync(0xFFFFFFFFu, ws_i, o);
        if (lane >= o) ws_i += t;
    }
    __shared__ int wsum[32];
    if (lane == 31) wsum[wid] = ws_i;
    __syncthreads();
    if (wid == 0) {
        int w = wsum[lane];
        #pragma unroll
        for (int o = 1; o < 32; o <<= 1) {
            int t = __shfl_up_sync(0xFFFFFFFFu, w, o);
            if (lane >= o) w += t;
        }
        wsum[lane] = w;
    }
    __syncthreads();
    int excl = g_bsum[b] + (ws_i - ts) + ((wid > 0) ? wsum[wid - 1] : 0);
    int e0 = excl, e1 = excl + t0, e2 = excl + t1, e3 = excl + t2;
    if (i0 < N_NODES)     { g_rowptr[i0] = e0;   g_cursor[i0] = e0;   g_norm[i0] = rsqrtf((float)v0 + 1.f); }
    if (i0 + 1 < N_NODES) { g_rowptr[i0+1] = e1; g_cursor[i0+1] = e1; g_norm[i0+1] = rsqrtf((float)v1 + 1.f); }
    if (i0 + 2 < N_NODES) { g_rowptr[i0+2] = e2; g_cursor[i0+2] = e2; g_norm[i0+2] = rsqrtf((float)v2 + 1.f); }
    if (i0 + 3 < N_NODES) { g_rowptr[i0+3] = e3; g_cursor[i0+3] = e3; g_norm[i0+3] = rsqrtf((float)v3 + 1.f); }
}

__global__ void scatter_kernel(const int* __restrict__ src, const int* __restrict__ dst) {
    int e = blockIdx.x * blockDim.x + threadIdx.x;
    if (e < N_EDGES) {
        int d = dst[e];
        int pos = atomicAdd(&g_cursor[d], 1);
        g_srcs[pos] = src[e];
    }
}

// ---------------- split-TF32 tensor-core GEMM: y = (hin @ W) * norm ----------------
// Block tile 128x128. K chunked 64+64. Splits hoisted to staging: smem holds
// interleaved (hi,lo) float2 so the mainloop is pure LDS.64 + HMMA.
// Error-compensated 3-pass: a*b ~= ahi*bhi + ahi*blo + alo*bhi.

#define KC 64
#define LDA2 68    // float2 pitch; 68 % 16 == 4 -> (4*gr+gc) bank phases bijective
#define LDB2 132   // float2 pitch; 132 % 16 == 4 -> (4*gc+gr) bank phases bijective
#define GEMM_SMEM ((128 * LDA2 + KC * LDB2) * 8)

__device__ __forceinline__ uint32_t f2tf32(float f) {
    uint32_t r;
    asm("cvt.rna.tf32.f32 %0, %1;" : "=r"(r) : "f"(f));
    return r;
}
__device__ __forceinline__ float2 split_tf32(float f) {
    uint32_t hi = f2tf32(f);
    float rem = f - __uint_as_float(hi);
    uint32_t lo = f2tf32(rem);
    return make_float2(__uint_as_float(hi), __uint_as_float(lo));
}
__device__ __forceinline__ void mma_tf32(float4& d, uint32_t a0, uint32_t a1,
                                         uint32_t a2, uint32_t a3,
                                         uint32_t b0, uint32_t b1) {
    asm volatile(
        "mma.sync.aligned.m16n8k8.row.col.f32.tf32.tf32.f32 "
        "{%0,%1,%2,%3}, {%4,%5,%6,%7}, {%8,%9}, {%0,%1,%2,%3};"
        : "+f"(d.x), "+f"(d.y), "+f"(d.z), "+f"(d.w)
        : "r"(a0), "r"(a1), "r"(a2), "r"(a3), "r"(b0), "r"(b1));
}

__global__ __launch_bounds__(256) void gemm_tf32_kernel(const float* __restrict__ x,
                                                        const float* __restrict__ W,
                                                        int first) {
    const float* __restrict__ hin = first ? x : g_h;
    extern __shared__ float2 sm2[];
    float2* As2 = sm2;                    // [128][LDA2]
    float2* Bs2 = sm2 + 128 * LDA2;       // [KC][LDB2]
    int tid = threadIdx.x;
    int m0 = blockIdx.x * 128;
    int lane = tid & 31, wid = tid >> 5;
    int warpM = wid >> 1, warpN = wid & 1;
    int mbase = warpM * 32, nbase = warpN * 64;
    int gr = lane >> 2, gc = lane & 3;

    float4 acc[2][8];
    #pragma unroll
    for (int mf = 0; mf < 2; mf++)
        #pragma unroll
        for (int nf = 0; nf < 8; nf++)
            acc[mf][nf] = make_float4(0.f, 0.f, 0.f, 0.f);

    #pragma unroll
    for (int kc = 0; kc < 2; kc++) {
        int k0c = kc * KC;
        if (kc) __syncthreads();   // previous chunk's compute done before restage
        // stage A chunk: 128 rows x 64 cols -> 2048 float4 reads, split to (hi,lo)
        #pragma unroll
        for (int i = 0; i < 8; i++) {
            int idx = tid + i * 256;
            int row = idx >> 4;
            int c4 = (idx & 15) << 2;
            float4 v = make_float4(0.f, 0.f, 0.f, 0.f);
            if (m0 + row < N_NODES)
                v = *reinterpret_cast<const float4*>(hin + (size_t)(m0 + row) * HID + k0c + c4);
            float2* p = As2 + row * LDA2 + c4;
            p[0] = split_tf32(v.x); p[1] = split_tf32(v.y);
            p[2] = split_tf32(v.z); p[3] = split_tf32(v.w);
        }
        // stage B chunk: 64 k-rows x 128 n-cols
        #pragma unroll
        for (int i = 0; i < 8; i++) {
            int idx = tid + i * 256;
            int kr = idx >> 5;
            int c4 = (idx & 31) << 2;
            float4 v = *reinterpret_cast<const float4*>(W + (size_t)(k0c + kr) * HID + c4);
            float2* p = Bs2 + kr * LDB2 + c4;
            p[0] = split_tf32(v.x); p[1] = split_tf32(v.y);
            p[2] = split_tf32(v.z); p[3] = split_tf32(v.w);
        }
        __syncthreads();

        #pragma unroll
        for (int ks = 0; ks < 8; ks++) {
            int k0 = ks * 8;
            float2 A[2][4];
            #pragma unroll
            for (int mf = 0; mf < 2; mf++) {
                int r = mbase + mf * 16 + gr;
                A[mf][0] = As2[r * LDA2 + k0 + gc];
                A[mf][1] = As2[(r + 8) * LDA2 + k0 + gc];
                A[mf][2] = As2[r * LDA2 + k0 + gc + 4];
                A[mf][3] = As2[(r + 8) * LDA2 + k0 + gc + 4];
            }
            float2 B[8][2];
            #pragma unroll
            for (int nf = 0; nf < 8; nf++) {
                int c = nbase + nf * 8 + gr;
                B[nf][0] = Bs2[(k0 + gc) * LDB2 + c];
                B[nf][1] = Bs2[(k0 + 4 + gc) * LDB2 + c];
            }
            #pragma unroll
            for (int mf = 0; mf < 2; mf++) {
                uint32_t ah0 = __float_as_uint(A[mf][0].x), al0 = __float_as_uint(A[mf][0].y);
                uint32_t ah1 = __float_as_uint(A[mf][1].x), al1 = __float_as_uint(A[mf][1].y);
                uint32_t ah2 = __float_as_uint(A[mf][2].x), al2 = __float_as_uint(A[mf][2].y);
                uint32_t ah3 = __float_as_uint(A[mf][3].x), al3 = __float_as_uint(A[mf][3].y);
                #pragma unroll
                for (int nf = 0; nf < 8; nf++) {
                    uint32_t bh0 = __float_as_uint(B[nf][0].x), bl0 = __float_as_uint(B[nf][0].y);
                    uint32_t bh1 = __float_as_uint(B[nf][1].x), bl1 = __float_as_uint(B[nf][1].y);
                    mma_tf32(acc[mf][nf], ah0, ah1, ah2, ah3, bh0, bh1);
                    mma_tf32(acc[mf][nf], ah0, ah1, ah2, ah3, bl0, bl1);
                    mma_tf32(acc[mf][nf], al0, al1, al2, al3, bh0, bh1);
                }
            }
        }
    }

    // epilogue: y = acc * norm[row]
    #pragma unroll
    for (int mf = 0; mf < 2; mf++) {
        int r0 = m0 + mbase + mf * 16 + gr;
        int r1 = r0 + 8;
        float n0 = (r0 < N_NODES) ? g_norm[r0] : 0.f;
        float n1 = (r1 < N_NODES) ? g_norm[r1] : 0.f;
        #pragma unroll
        for (int nf = 0; nf < 8; nf++) {
            int c = nbase + nf * 8 + gc * 2;
            if (r0 < N_NODES) {
                float2 v = make_float2(acc[mf][nf].x * n0, acc[mf][nf].y * n0);
                *reinterpret_cast<float2*>(g_y + (size_t)r0 * HID + c) = v;
            }
            if (r1 < N_NODES) {
                float2 v = make_float2(acc[mf][nf].z * n1, acc[mf][nf].w * n1);
                *reinterpret_cast<float2*>(g_y + (size_t)r1 * HID + c) = v;
            }
        }
    }
}

// ---------------- aggregation + BN(eval) + ReLU, warp per node ----------------
// last!=0: fuse global-mean-pool (atomicAdd into g_pool) instead of writing g_h.
__global__ __launch_bounds__(256) void agg_kernel(const float* __restrict__ bs,
                                                  const float* __restrict__ gam,
                                                  const float* __restrict__ bet,
                                                  const float* __restrict__ mean,
                                                  const float* __restrict__ var,
                                                  const int* __restrict__ batch,
                                                  int last) {
    int wid = threadIdx.x >> 5, lane = threadIdx.x & 31;
    int n = blockIdx.x * 8 + wid;
    if (n >= N_NODES) return;
    const float4* __restrict__ y4 = reinterpret_cast<const float4*>(g_y);

    float4 acc = y4[n * 32 + lane];            // self term: norm^2*xw = norm*y[n]
    int e0 = g_rowptr[n], e1 = g_rowptr[n + 1];
    for (int e = e0; e < e1; e++) {
        int s = g_srcs[e];
        float4 v = y4[s * 32 + lane];
        acc.x += v.x; acc.y += v.y; acc.z += v.z; acc.w += v.w;
    }
    float nrm = g_norm[n];
    int j = lane * 4;
    float4 b4 = *reinterpret_cast<const float4*>(bs + j);
    float4 g4 = *reinterpret_cast<const float4*>(gam + j);
    float4 be4 = *reinterpret_cast<const float4*>(bet + j);
    float4 m4 = *reinterpret_cast<const float4*>(mean + j);
    float4 v4 = *reinterpret_cast<const float4*>(var + j);
    float4 r;
    r.x = fmaxf((nrm * acc.x + b4.x - m4.x) * (g4.x * rsqrtf(v4.x + BN_EPS)) + be4.x, 0.f);
    r.y = fmaxf((nrm * acc.y + b4.y - m4.y) * (g4.y * rsqrtf(v4.y + BN_EPS)) + be4.y, 0.f);
    r.z = fmaxf((nrm * acc.z + b4.z - m4.z) * (g4.z * rsqrtf(v4.z + BN_EPS)) + be4.z, 0.f);
    r.w = fmaxf((nrm * acc.w + b4.w - m4.w) * (g4.w * rsqrtf(v4.w + BN_EPS)) + be4.w, 0.f);
    if (!last) {
        reinterpret_cast<float4*>(g_h)[n * 32 + lane] = r;
    } else {
        int b = batch[n];
        float* p = &g_pool[b * HID + lane * 4];
        atomicAdd(p, r.x); atomicAdd(p + 1, r.y);
        atomicAdd(p + 2, r.z); atomicAdd(p + 3, r.w);
        if (lane == 0) atomicAdd(&g_cnt[b], 1.0f);
    }
}

// ---------------- final projection: out[g] = pooled[g] @ W_out + b_out ----------------
__global__ __launch_bounds__(128) void out_kernel(const float* __restrict__ W_out,
                                                  const float* __restrict__ b_out,
                                                  float* __restrict__ out) {
    int g = blockIdx.x;
    int tid = threadIdx.x;
    int lane = tid & 31, wid = tid >> 5;
    float cnt = fmaxf(g_cnt[g], 1.0f);
    float p = g_pool[g * HID + tid] / cnt;
    float v[5];
    #pragma unroll
    for (int o = 0; o < 5; o++) v[o] = p * W_out[tid * 5 + o];
    #pragma unroll
    for (int o = 0; o < 5; o++)
        #pragma unroll
        for (int off = 16; off > 0; off >>= 1)
            v[o] += __shfl_down_sync(0xFFFFFFFFu, v[o], off);
    __shared__ float sred[4][5];
    if (lane == 0) {
        #pragma unroll
        for (int o = 0; o < 5; o++) sred[wid][o] = v[o];
    }
    __syncthreads();
    if (tid < 5) {
        float s = sred[0][tid] + sred[1][tid] + sred[2][tid] + sred[3][tid] + b_out[tid];
        out[g * 5 + tid] = s;
    }
}

// ---------------- launch ----------------
extern "C" void kernel_launch(void* const* d_in, const int* in_sizes, int n_in,
                              void* d_out, int out_size) {
    const float* x      = (const float*)d_in[0];
    const int*   edge   = (const int*)d_in[1];
    const int*   batch  = (const int*)d_in[2];
    const float* Ws     = (const float*)d_in[3];
    const float* bs     = (const float*)d_in[4];
    const float* gammas = (const float*)d_in[5];
    const float* betas  = (const float*)d_in[6];
    const float* rmean  = (const float*)d_in[7];
    const float* rvar   = (const float*)d_in[8];
    const float* W_out  = (const float*)d_in[9];
    const float* b_out  = (const float*)d_in[10];
    const int* src = edge;
    const int* dst = edge + N_EDGES;

    cudaFuncSetAttribute(gemm_tf32_kernel,
                         cudaFuncAttributeMaxDynamicSharedMemorySize, GEMM_SMEM);

    init_kernel<<<256, 256>>>();
    count_kernel<<<(N_EDGES + 255) / 256, 256>>>(dst);
    scan_reduce_kernel<<<SCAN_NB, 256>>>();
    scan_partials_kernel<<<1, 32>>>();
    scan_final_kernel<<<SCAN_NB, 1024>>>();
    scatter_kernel<<<(N_EDGES + 255) / 256, 256>>>(src, dst);

    int gemm_blocks = (N_NODES + 127) / 128;
    int node_warp_blocks = (N_NODES + 7) / 8;
    for (int l = 0; l < 4; l++) {
        gemm_tf32_kernel<<<gemm_blocks, 256, GEMM_SMEM>>>(x, Ws + l * HID * HID,
                                                          l == 0 ? 1 : 0);
        agg_kernel<<<node_warp_blocks, 256>>>(bs + l * HID, gammas + l * HID,
                                              betas + l * HID, rmean + l * HID,
                                              rvar + l * HID, batch,
                                              l == 3 ? 1 : 0);
    }
    out_kernel<<<N_GRAPHS, 128>>>(W_out, b_out, (float*)d_out);
}

// round 9
// speedup vs baseline: 1.2275x; 1.0803x over previous
#include <cuda_runtime.h>
#include <cuda_fp16.h>
#include <cstdint>

#define N_NODES 100000
#define N_EDGES 1600000
#define N_GRAPHS 2000
#define HID 128
#define BN_EPS 1e-5f

// ---------------- scratch (device globals; no allocation allowed) ----------------
__device__ __half g_yh[N_NODES * HID];    // y = (h @ W) * norm, fp16 (25.6 MB)
__device__ float g_h[N_NODES * HID];      // activations fp32       (51.2 MB)
__device__ float g_norm[N_NODES];
__device__ int   g_deg[N_NODES];
__device__ int   g_rowptr[N_NODES + 1];
__device__ int   g_cursor[N_NODES];
__device__ int   g_srcs[N_EDGES];         // CSR by dst (6.4 MB)
__device__ float g_pool[N_GRAPHS * HID];
__device__ float g_cnt[N_GRAPHS];

#define SCAN_BLK 4096
#define SCAN_NB ((N_NODES + SCAN_BLK - 1) / SCAN_BLK)   // 25
__device__ int g_bsum[SCAN_NB];

// ---------------- setup kernels ----------------
__global__ void init_kernel() {
    int i = blockIdx.x * blockDim.x + threadIdx.x;
    int stride = gridDim.x * blockDim.x;
    for (int t = i; t < N_GRAPHS * HID; t += stride) g_pool[t] = 0.f;
    for (int t = i; t < N_NODES; t += stride) g_deg[t] = 0;
    for (int t = i; t < N_GRAPHS; t += stride) g_cnt[t] = 0.f;
}

__global__ void count_kernel(const int* __restrict__ dst) {
    int e = blockIdx.x * blockDim.x + threadIdx.x;
    if (e < N_EDGES) atomicAdd(&g_deg[dst[e]], 1);
}

// ---- 3-phase prefix scan over g_deg -> rowptr/cursor + norm ----
__global__ __launch_bounds__(256) void scan_reduce_kernel() {
    int b = blockIdx.x;
    int base = b * SCAN_BLK;
    int tid = threadIdx.x;
    int sum = 0;
    for (int i = tid; i < SCAN_BLK; i += 256) {
        int idx = base + i;
        if (idx < N_NODES) sum += g_deg[idx];
    }
    #pragma unroll
    for (int o = 16; o > 0; o >>= 1) sum += __shfl_down_sync(0xFFFFFFFFu, sum, o);
    __shared__ int ws[8];
    int lane = tid & 31, wid = tid >> 5;
    if (lane == 0) ws[wid] = sum;
    __syncthreads();
    if (tid == 0) {
        int t = 0;
        #pragma unroll
        for (int i = 0; i < 8; i++) t += ws[i];
        g_bsum[b] = t;
    }
}

__global__ void scan_partials_kernel() {
    int lane = threadIdx.x;
    int v = (lane < SCAN_NB) ? g_bsum[lane] : 0;
    int x = v;
    #pragma unroll
    for (int o = 1; o < 32; o <<= 1) {
        int t = __shfl_up_sync(0xFFFFFFFFu, x, o);
        if (lane >= o) x += t;
    }
    if (lane < SCAN_NB) g_bsum[lane] = x - v;   // exclusive
    if (lane == 31) g_rowptr[N_NODES] = x;      // total (lane31 inclusive = full sum)
}

__global__ __launch_bounds__(1024) void scan_final_kernel() {
    int b = blockIdx.x;
    int base = b * SCAN_BLK;
    int tid = threadIdx.x;
    int lane = tid & 31, wid = tid >> 5;
    int i0 = base + tid * 4;
    int v0 = 0, v1 = 0, v2 = 0, v3 = 0;
    if (i0 + 3 < N_NODES) {
        int4 v = *reinterpret_cast<const int4*>(&g_deg[i0]);
        v0 = v.x; v1 = v.y; v2 = v.z; v3 = v.w;
    } else {
        if (i0 < N_NODES) v0 = g_deg[i0];
        if (i0 + 1 < N_NODES) v1 = g_deg[i0 + 1];
        if (i0 + 2 < N_NODES) v2 = g_deg[i0 + 2];
        if (i0 + 3 < N_NODES) v3 = g_deg[i0 + 3];
    }
    int t0 = v0, t1 = t0 + v1, t2 = t1 + v2, t3 = t2 + v3;
    int ts = t3;
    int ws_i = ts;
    #pragma unroll
    for (int o = 1; o < 32; o <<= 1) {
        int t = __shfl_up_sync(0xFFFFFFFFu, ws_i, o);
        if (lane >= o) ws_i += t;
    }
    __shared__ int wsum[32];
    if (lane == 31) wsum[wid] = ws_i;
    __syncthreads();
    if (wid == 0) {
        int w = wsum[lane];
        #pragma unroll
        for (int o = 1; o < 32; o <<= 1) {
            int t = __shfl_up_sync(0xFFFFFFFFu, w, o);
            if (lane >= o) w += t;
        }
        wsum[lane] = w;
    }
    __syncthreads();
    int excl = g_bsum[b] + (ws_i - ts) + ((wid > 0) ? wsum[wid - 1] : 0);
    int e0 = excl, e1 = excl + t0, e2 = excl + t1, e3 = excl + t2;
    if (i0 < N_NODES)     { g_rowptr[i0] = e0;   g_cursor[i0] = e0;   g_norm[i0] = rsqrtf((float)v0 + 1.f); }
    if (i0 + 1 < N_NODES) { g_rowptr[i0+1] = e1; g_cursor[i0+1] = e1; g_norm[i0+1] = rsqrtf((float)v1 + 1.f); }
    if (i0 + 2 < N_NODES) { g_rowptr[i0+2] = e2; g_cursor[i0+2] = e2; g_norm[i0+2] = rsqrtf((float)v2 + 1.f); }
    if (i0 + 3 < N_NODES) { g_rowptr[i0+3] = e3; g_cursor[i0+3] = e3; g_norm[i0+3] = rsqrtf((float)v3 + 1.f); }
}

__global__ void scatter_kernel(const int* __restrict__ src, const int* __restrict__ dst) {
    int e = blockIdx.x * blockDim.x + threadIdx.x;
    if (e < N_EDGES) {
        int d = dst[e];
        int pos = atomicAdd(&g_cursor[d], 1);
        g_srcs[pos] = src[e];
    }
}

// ---------------- split-TF32 tensor-core GEMM: y = (hin @ W) * norm -> fp16 ----------------
// Block tile 128x128. K chunked 64+64. Splits hoisted to staging: smem holds
// interleaved (hi,lo) float2 so the mainloop is pure LDS.64 + HMMA.
// Error-compensated 3-pass: a*b ~= ahi*bhi + ahi*blo + alo*bhi.

#define KC 64
#define LDA2 68    // float2 pitch; 68 % 16 == 4 -> (4*gr+gc) bank phases bijective
#define LDB2 132   // float2 pitch; 132 % 16 == 4 -> (4*gc+gr) bank phases bijective
#define GEMM_SMEM ((128 * LDA2 + KC * LDB2) * 8)

__device__ __forceinline__ uint32_t f2tf32(float f) {
    uint32_t r;
    asm("cvt.rna.tf32.f32 %0, %1;" : "=r"(r) : "f"(f));
    return r;
}
__device__ __forceinline__ float2 split_tf32(float f) {
    uint32_t hi = f2tf32(f);
    float rem = f - __uint_as_float(hi);
    uint32_t lo = f2tf32(rem);
    return make_float2(__uint_as_float(hi), __uint_as_float(lo));
}
__device__ __forceinline__ void mma_tf32(float4& d, uint32_t a0, uint32_t a1,
                                         uint32_t a2, uint32_t a3,
                                         uint32_t b0, uint32_t b1) {
    asm volatile(
        "mma.sync.aligned.m16n8k8.row.col.f32.tf32.tf32.f32 "
        "{%0,%1,%2,%3}, {%4,%5,%6,%7}, {%8,%9}, {%0,%1,%2,%3};"
        : "+f"(d.x), "+f"(d.y), "+f"(d.z), "+f"(d.w)
        : "r"(a0), "r"(a1), "r"(a2), "r"(a3), "r"(b0), "r"(b1));
}

__global__ __launch_bounds__(256) void gemm_tf32_kernel(const float* __restrict__ x,
                                                        const float* __restrict__ W,
                                                        int first) {
    const float* __restrict__ hin = first ? x : g_h;
    extern __shared__ float2 sm2[];
    float2* As2 = sm2;                    // [128][LDA2]
    float2* Bs2 = sm2 + 128 * LDA2;       // [KC][LDB2]
    int tid = threadIdx.x;
    int m0 = blockIdx.x * 128;
    int lane = tid & 31, wid = tid >> 5;
    int warpM = wid >> 1, warpN = wid & 1;
    int mbase = warpM * 32, nbase = warpN * 64;
    int gr = lane >> 2, gc = lane & 3;

    float4 acc[2][8];
    #pragma unroll
    for (int mf = 0; mf < 2; mf++)
        #pragma unroll
        for (int nf = 0; nf < 8; nf++)
            acc[mf][nf] = make_float4(0.f, 0.f, 0.f, 0.f);

    #pragma unroll
    for (int kc = 0; kc < 2; kc++) {
        int k0c = kc * KC;
        if (kc) __syncthreads();   // previous chunk's compute done before restage
        // stage A chunk: 128 rows x 64 cols -> 2048 float4 reads, split to (hi,lo)
        #pragma unroll
        for (int i = 0; i < 8; i++) {
            int idx = tid + i * 256;
            int row = idx >> 4;
            int c4 = (idx & 15) << 2;
            float4 v = make_float4(0.f, 0.f, 0.f, 0.f);
            if (m0 + row < N_NODES)
                v = *reinterpret_cast<const float4*>(hin + (size_t)(m0 + row) * HID + k0c + c4);
            float2* p = As2 + row * LDA2 + c4;
            p[0] = split_tf32(v.x); p[1] = split_tf32(v.y);
            p[2] = split_tf32(v.z); p[3] = split_tf32(v.w);
        }
        // stage B chunk: 64 k-rows x 128 n-cols
        #pragma unroll
        for (int i = 0; i < 8; i++) {
            int idx = tid + i * 256;
            int kr = idx >> 5;
            int c4 = (idx & 31) << 2;
            float4 v = *reinterpret_cast<const float4*>(W + (size_t)(k0c + kr) * HID + c4);
            float2* p = Bs2 + kr * LDB2 + c4;
            p[0] = split_tf32(v.x); p[1] = split_tf32(v.y);
            p[2] = split_tf32(v.z); p[3] = split_tf32(v.w);
        }
        __syncthreads();

        #pragma unroll
        for (int ks = 0; ks < 8; ks++) {
            int k0 = ks * 8;
            float2 A[2][4];
            #pragma unroll
            for (int mf = 0; mf < 2; mf++) {
                int r = mbase + mf * 16 + gr;
                A[mf][0] = As2[r * LDA2 + k0 + gc];
                A[mf][1] = As2[(r + 8) * LDA2 + k0 + gc];
                A[mf][2] = As2[r * LDA2 + k0 + gc + 4];
                A[mf][3] = As2[(r + 8) * LDA2 + k0 + gc + 4];
            }
            float2 B[8][2];
            #pragma unroll
            for (int nf = 0; nf < 8; nf++) {
                int c = nbase + nf * 8 + gr;
                B[nf][0] = Bs2[(k0 + gc) * LDB2 + c];
                B[nf][1] = Bs2[(k0 + 4 + gc) * LDB2 + c];
            }
            #pragma unroll
            for (int mf = 0; mf < 2; mf++) {
                uint32_t ah0 = __float_as_uint(A[mf][0].x), al0 = __float_as_uint(A[mf][0].y);
                uint32_t ah1 = __float_as_uint(A[mf][1].x), al1 = __float_as_uint(A[mf][1].y);
                uint32_t ah2 = __float_as_uint(A[mf][2].x), al2 = __float_as_uint(A[mf][2].y);
                uint32_t ah3 = __float_as_uint(A[mf][3].x), al3 = __float_as_uint(A[mf][3].y);
                #pragma unroll
                for (int nf = 0; nf < 8; nf++) {
                    uint32_t bh0 = __float_as_uint(B[nf][0].x), bl0 = __float_as_uint(B[nf][0].y);
                    uint32_t bh1 = __float_as_uint(B[nf][1].x), bl1 = __float_as_uint(B[nf][1].y);
                    mma_tf32(acc[mf][nf], ah0, ah1, ah2, ah3, bh0, bh1);
                    mma_tf32(acc[mf][nf], ah0, ah1, ah2, ah3, bl0, bl1);
                    mma_tf32(acc[mf][nf], al0, al1, al2, al3, bh0, bh1);
                }
            }
        }
    }

    // epilogue: y = acc * norm[row], stored fp16
    #pragma unroll
    for (int mf = 0; mf < 2; mf++) {
        int r0 = m0 + mbase + mf * 16 + gr;
        int r1 = r0 + 8;
        float n0 = (r0 < N_NODES) ? g_norm[r0] : 0.f;
        float n1 = (r1 < N_NODES) ? g_norm[r1] : 0.f;
        #pragma unroll
        for (int nf = 0; nf < 8; nf++) {
            int c = nbase + nf * 8 + gc * 2;
            if (r0 < N_NODES) {
                __half2 v = __floats2half2_rn(acc[mf][nf].x * n0, acc[mf][nf].y * n0);
                *reinterpret_cast<__half2*>(g_yh + (size_t)r0 * HID + c) = v;
            }
            if (r1 < N_NODES) {
                __half2 v = __floats2half2_rn(acc[mf][nf].z * n1, acc[mf][nf].w * n1);
                *reinterpret_cast<__half2*>(g_yh + (size_t)r1 * HID + c) = v;
            }
        }
    }
}

// ---------------- aggregation + BN(eval) + ReLU, warp per node, fp16 gather ----------------
// last!=0: fuse global-mean-pool (atomicAdd into g_pool) instead of writing g_h.
__global__ __launch_bounds__(256) void agg_kernel(const float* __restrict__ bs,
                                                  const float* __restrict__ gam,
                                                  const float* __restrict__ bet,
                                                  const float* __restrict__ mean,
                                                  const float* __restrict__ var,
                                                  const int* __restrict__ batch,
                                                  int last) {
    int wid = threadIdx.x >> 5, lane = threadIdx.x & 31;
    int n = blockIdx.x * 8 + wid;
    if (n >= N_NODES) return;
    const uint2* __restrict__ y2 = reinterpret_cast<const uint2*>(g_yh); // 4 halves / uint2

    uint2 sraw = y2[n * 32 + lane];            // self term: norm^2*xw = norm*y[n]
    float2 s0 = __half22float2(*reinterpret_cast<const __half2*>(&sraw.x));
    float2 s1 = __half22float2(*reinterpret_cast<const __half2*>(&sraw.y));
    float4 acc = make_float4(s0.x, s0.y, s1.x, s1.y);

    int e0 = g_rowptr[n], e1 = g_rowptr[n + 1];
    for (int e = e0; e < e1; e++) {
        int s = g_srcs[e];
        uint2 raw = y2[s * 32 + lane];
        float2 f0 = __half22float2(*reinterpret_cast<const __half2*>(&raw.x));
        float2 f1 = __half22float2(*reinterpret_cast<const __half2*>(&raw.y));
        acc.x += f0.x; acc.y += f0.y; acc.z += f1.x; acc.w += f1.y;
    }
    float nrm = g_norm[n];
    int j = lane * 4;
    float4 b4 = *reinterpret_cast<const float4*>(bs + j);
    float4 g4 = *reinterpret_cast<const float4*>(gam + j);
    float4 be4 = *reinterpret_cast<const float4*>(bet + j);
    float4 m4 = *reinterpret_cast<const float4*>(mean + j);
    float4 v4 = *reinterpret_cast<const float4*>(var + j);
    float4 r;
    r.x = fmaxf((nrm * acc.x + b4.x - m4.x) * (g4.x * rsqrtf(v4.x + BN_EPS)) + be4.x, 0.f);
    r.y = fmaxf((nrm * acc.y + b4.y - m4.y) * (g4.y * rsqrtf(v4.y + BN_EPS)) + be4.y, 0.f);
    r.z = fmaxf((nrm * acc.z + b4.z - m4.z) * (g4.z * rsqrtf(v4.z + BN_EPS)) + be4.z, 0.f);
    r.w = fmaxf((nrm * acc.w + b4.w - m4.w) * (g4.w * rsqrtf(v4.w + BN_EPS)) + be4.w, 0.f);
    if (!last) {
        reinterpret_cast<float4*>(g_h)[n * 32 + lane] = r;
    } else {
        int b = batch[n];
        float* p = &g_pool[b * HID + lane * 4];
        atomicAdd(p, r.x); atomicAdd(p + 1, r.y);
        atomicAdd(p + 2, r.z); atomicAdd(p + 3, r.w);
        if (lane == 0) atomicAdd(&g_cnt[b], 1.0f);
    }
}

// ---------------- final projection: out[g] = pooled[g] @ W_out + b_out ----------------
__global__ __launch_bounds__(128) void out_kernel(const float* __restrict__ W_out,
                                                  const float* __restrict__ b_out,
                                                  float* __restrict__ out) {
    int g = blockIdx.x;
    int tid = threadIdx.x;
    int lane = tid & 31, wid = tid >> 5;
    float cnt = fmaxf(g_cnt[g], 1.0f);
    float p = g_pool[g * HID + tid] / cnt;
    float v[5];
    #pragma unroll
    for (int o = 0; o < 5; o++) v[o] = p * W_out[tid * 5 + o];
    #pragma unroll
    for (int o = 0; o < 5; o++)
        #pragma unroll
        for (int off = 16; off > 0; off >>= 1)
            v[o] += __shfl_down_sync(0xFFFFFFFFu, v[o], off);
    __shared__ float sred[4][5];
    if (lane == 0) {
        #pragma unroll
        for (int o = 0; o < 5; o++) sred[wid][o] = v[o];
    }
    __syncthreads();
    if (tid < 5) {
        float s = sred[0][tid] + sred[1][tid] + sred[2][tid] + sred[3][tid] + b_out[tid];
        out[g * 5 + tid] = s;
    }
}

// ---------------- launch ----------------
extern "C" void kernel_launch(void* const* d_in, const int* in_sizes, int n_in,
                              void* d_out, int out_size) {
    const float* x      = (const float*)d_in[0];
    const int*   edge   = (const int*)d_in[1];
    const int*   batch  = (const int*)d_in[2];
    const float* Ws     = (const float*)d_in[3];
    const float* bs     = (const float*)d_in[4];
    const float* gammas = (const float*)d_in[5];
    const float* betas  = (const float*)d_in[6];
    const float* rmean  = (const float*)d_in[7];
    const float* rvar   = (const float*)d_in[8];
    const float* W_out  = (const float*)d_in[9];
    const float* b_out  = (const float*)d_in[10];
    const int* src = edge;
    const int* dst = edge + N_EDGES;

    cudaFuncSetAttribute(gemm_tf32_kernel,
                         cudaFuncAttributeMaxDynamicSharedMemorySize, GEMM_SMEM);

    init_kernel<<<256, 256>>>();
    count_kernel<<<(N_EDGES + 255) / 256, 256>>>(dst);
    scan_reduce_kernel<<<SCAN_NB, 256>>>();
    scan_partials_kernel<<<1, 32>>>();
    scan_final_kernel<<<SCAN_NB, 1024>>>();
    scatter_kernel<<<(N_EDGES + 255) / 256, 256>>>(src, dst);

    int gemm_blocks = (N_NODES + 127) / 128;
    int node_warp_blocks = (N_NODES + 7) / 8;
    for (int l = 0; l < 4; l++) {
        gemm_tf32_kernel<<<gemm_blocks, 256, GEMM_SMEM>>>(x, Ws + l * HID * HID,
                                                          l == 0 ? 1 : 0);
        agg_kernel<<<node_warp_blocks, 256>>>(bs + l * HID, gammas + l * HID,
                                              betas + l * HID, rmean + l * HID,
                                              rvar + l * HID, batch,
                                              l == 3 ? 1 : 0);
    }
    out_kernel<<<N_GRAPHS, 128>>>(W_out, b_out, (float*)d_out);
}

// round 12
// speedup vs baseline: 1.4115x; 1.1499x over previous
#include <cuda_runtime.h>
#include <cuda_fp16.h>
#include <cstdint>

#define N_NODES 100000
#define N_EDGES 1600000
#define N_GRAPHS 2000
#define HID 128
#define BN_EPS 1e-5f

// ---------------- scratch (device globals; no allocation allowed) ----------------
__device__ __half g_yh[N_NODES * HID];    // y = (h @ W) * norm, fp16 (25.6 MB)
__device__ __half g_hh[N_NODES * HID];    // activations fp16        (25.6 MB)
__device__ float g_norm[N_NODES];
__device__ int   g_deg[N_NODES];
__device__ int   g_rowptr[N_NODES + 1];
__device__ int   g_cursor[N_NODES];
__device__ int   g_srcs[N_EDGES];         // CSR by dst (6.4 MB)
__device__ float g_pool[N_GRAPHS * HID];
__device__ float g_cnt[N_GRAPHS];

#define SCAN_BLK 4096
#define SCAN_NB ((N_NODES + SCAN_BLK - 1) / SCAN_BLK)   // 25
__device__ int g_bsum[SCAN_NB];

// ---------------- setup kernels ----------------
__global__ void init_kernel() {
    int i = blockIdx.x * blockDim.x + threadIdx.x;
    int stride = gridDim.x * blockDim.x;
    for (int t = i; t < N_GRAPHS * HID; t += stride) g_pool[t] = 0.f;
    for (int t = i; t < N_NODES; t += stride) g_deg[t] = 0;
    for (int t = i; t < N_GRAPHS; t += stride) g_cnt[t] = 0.f;
}

__global__ void count_kernel(const int* __restrict__ dst) {
    int e = blockIdx.x * blockDim.x + threadIdx.x;
    if (e < N_EDGES) atomicAdd(&g_deg[dst[e]], 1);
}

// ---- 3-phase prefix scan over g_deg -> rowptr/cursor + norm ----
__global__ __launch_bounds__(256) void scan_reduce_kernel() {
    int b = blockIdx.x;
    int base = b * SCAN_BLK;
    int tid = threadIdx.x;
    int sum = 0;
    for (int i = tid; i < SCAN_BLK; i += 256) {
        int idx = base + i;
        if (idx < N_NODES) sum += g_deg[idx];
    }
    #pragma unroll
    for (int o = 16; o > 0; o >>= 1) sum += __shfl_down_sync(0xFFFFFFFFu, sum, o);
    __shared__ int ws[8];
    int lane = tid & 31, wid = tid >> 5;
    if (lane == 0) ws[wid] = sum;
    __syncthreads();
    if (tid == 0) {
        int t = 0;
        #pragma unroll
        for (int i = 0; i < 8; i++) t += ws[i];
        g_bsum[b] = t;
    }
}

__global__ void scan_partials_kernel() {
    int lane = threadIdx.x;
    int v = (lane < SCAN_NB) ? g_bsum[lane] : 0;
    int x = v;
    #pragma unroll
    for (int o = 1; o < 32; o <<= 1) {
        int t = __shfl_up_sync(0xFFFFFFFFu, x, o);
        if (lane >= o) x += t;
    }
    if (lane < SCAN_NB) g_bsum[lane] = x - v;   // exclusive
    if (lane == 31) g_rowptr[N_NODES] = x;
}

__global__ __launch_bounds__(1024) void scan_final_kernel() {
    int b = blockIdx.x;
    int base = b * SCAN_BLK;
    int tid = threadIdx.x;
    int lane = tid & 31, wid = tid >> 5;
    int i0 = base + tid * 4;
    int v0 = 0, v1 = 0, v2 = 0, v3 = 0;
    if (i0 + 3 < N_NODES) {
        int4 v = *reinterpret_cast<const int4*>(&g_deg[i0]);
        v0 = v.x; v1 = v.y; v2 = v.z; v3 = v.w;
    } else {
        if (i0 < N_NODES) v0 = g_deg[i0];
        if (i0 + 1 < N_NODES) v1 = g_deg[i0 + 1];
        if (i0 + 2 < N_NODES) v2 = g_deg[i0 + 2];
        if (i0 + 3 < N_NODES) v3 = g_deg[i0 + 3];
    }
    int t0 = v0, t1 = t0 + v1, t2 = t1 + v2, t3 = t2 + v3;
    int ts = t3;
    int ws_i = ts;
    #pragma unroll
    for (int o = 1; o < 32; o <<= 1) {
        int t = __shfl_up_sync(0xFFFFFFFFu, ws_i, o);
        if (lane >= o) ws_i += t;
    }
    __shared__ int wsum[32];
    if (lane == 31) wsum[wid] = ws_i;
    __syncthreads();
    if (wid == 0) {
        int w = wsum[lane];
        #pragma unroll
        for (int o = 1; o < 32; o <<= 1) {
            int t = __shfl_up_sync(0xFFFFFFFFu, w, o);
            if (lane >= o) w += t;
        }
        wsum[lane] = w;
    }
    __syncthreads();
    int excl = g_bsum[b] + (ws_i - ts) + ((wid > 0) ? wsum[wid - 1] : 0);
    int e0 = excl, e1 = excl + t0, e2 = excl + t1, e3 = excl + t2;
    if (i0 < N_NODES)     { g_rowptr[i0] = e0;   g_cursor[i0] = e0;   g_norm[i0] = rsqrtf((float)v0 + 1.f); }
    if (i0 + 1 < N_NODES) { g_rowptr[i0+1] = e1; g_cursor[i0+1] = e1; g_norm[i0+1] = rsqrtf((float)v1 + 1.f); }
    if (i0 + 2 < N_NODES) { g_rowptr[i0+2] = e2; g_cursor[i0+2] = e2; g_norm[i0+2] = rsqrtf((float)v2 + 1.f); }
    if (i0 + 3 < N_NODES) { g_rowptr[i0+3] = e3; g_cursor[i0+3] = e3; g_norm[i0+3] = rsqrtf((float)v3 + 1.f); }
}

__global__ void scatter_kernel(const int* __restrict__ src, const int* __restrict__ dst) {
    int e = blockIdx.x * blockDim.x + threadIdx.x;
    if (e < N_EDGES) {
        int d = dst[e];
        int pos = atomicAdd(&g_cursor[d], 1);
        g_srcs[pos] = src[e];
    }
}

// ---------------- GEMM common pieces ----------------
#define KC 64
#define LDAF 68    // float pitch for A (fp16-exact path); (4*gr+gc) banks bijective
#define LDA2 68    // float2 pitch for layer-0 split A
#define LDB2 132   // float2 pitch for split B
#define GEMM_L0_SMEM ((128 * LDA2 + KC * LDB2) * 8)
#define GEMM_F16_SMEM (128 * LDAF * 4 + KC * LDB2 * 8)

__device__ __forceinline__ uint32_t f2tf32(float f) {
    uint32_t r;
    asm("cvt.rna.tf32.f32 %0, %1;" : "=r"(r) : "f"(f));
    return r;
}
__device__ __forceinline__ float2 split_tf32(float f) {
    uint32_t hi = f2tf32(f);
    float rem = f - __uint_as_float(hi);
    uint32_t lo = f2tf32(rem);
    return make_float2(__uint_as_float(hi), __uint_as_float(lo));
}
__device__ __forceinline__ void mma_tf32(float4& d, uint32_t a0, uint32_t a1,
                                         uint32_t a2, uint32_t a3,
                                         uint32_t b0, uint32_t b1) {
    asm volatile(
        "mma.sync.aligned.m16n8k8.row.col.f32.tf32.tf32.f32 "
        "{%0,%1,%2,%3}, {%4,%5,%6,%7}, {%8,%9}, {%0,%1,%2,%3};"
        : "+f"(d.x), "+f"(d.y), "+f"(d.z), "+f"(d.w)
        : "r"(a0), "r"(a1), "r"(a2), "r"(a3), "r"(b0), "r"(b1));
}

// ---------------- layer-0 GEMM: y = (x @ W) * norm -> fp16 (3-pass split) ----------------
__global__ __launch_bounds__(256) void gemm_l0_kernel(const float* __restrict__ x,
                                                      const float* __restrict__ W) {
    extern __shared__ float2 sm2[];
    float2* As2 = sm2;                    // [128][LDA2]
    float2* Bs2 = sm2 + 128 * LDA2;       // [KC][LDB2]
    int tid = threadIdx.x;
    int m0 = blockIdx.x * 128;
    int lane = tid & 31, wid = tid >> 5;
    int warpM = wid >> 1, warpN = wid & 1;
    int mbase = warpM * 32, nbase = warpN * 64;
    int gr = lane >> 2, gc = lane & 3;

    float4 acc[2][8];
    #pragma unroll
    for (int mf = 0; mf < 2; mf++)
        #pragma unroll
        for (int nf = 0; nf < 8; nf++)
            acc[mf][nf] = make_float4(0.f, 0.f, 0.f, 0.f);

    #pragma unroll
    for (int kc = 0; kc < 2; kc++) {
        int k0c = kc * KC;
        if (kc) __syncthreads();
        #pragma unroll
        for (int i = 0; i < 8; i++) {
            int idx = tid + i * 256;
            int row = idx >> 4;
            int c4 = (idx & 15) << 2;
            float4 v = make_float4(0.f, 0.f, 0.f, 0.f);
            if (m0 + row < N_NODES)
                v = *reinterpret_cast<const float4*>(x + (size_t)(m0 + row) * HID + k0c + c4);
            float2* p = As2 + row * LDA2 + c4;
            p[0] = split_tf32(v.x); p[1] = split_tf32(v.y);
            p[2] = split_tf32(v.z); p[3] = split_tf32(v.w);
        }
        #pragma unroll
        for (int i = 0; i < 8; i++) {
            int idx = tid + i * 256;
            int kr = idx >> 5;
            int c4 = (idx & 31) << 2;
            float4 v = *reinterpret_cast<const float4*>(W + (size_t)(k0c + kr) * HID + c4);
            float2* p = Bs2 + kr * LDB2 + c4;
            p[0] = split_tf32(v.x); p[1] = split_tf32(v.y);
            p[2] = split_tf32(v.z); p[3] = split_tf32(v.w);
        }
        __syncthreads();

        #pragma unroll
        for (int ks = 0; ks < 8; ks++) {
            int k0 = ks * 8;
            float2 A[2][4];
            #pragma unroll
            for (int mf = 0; mf < 2; mf++) {
                int r = mbase + mf * 16 + gr;
                A[mf][0] = As2[r * LDA2 + k0 + gc];
                A[mf][1] = As2[(r + 8) * LDA2 + k0 + gc];
                A[mf][2] = As2[r * LDA2 + k0 + gc + 4];
                A[mf][3] = As2[(r + 8) * LDA2 + k0 + gc + 4];
            }
            #pragma unroll
            for (int nf = 0; nf < 8; nf++) {
                int c = nbase + nf * 8 + gr;
                float2 B0 = Bs2[(k0 + gc) * LDB2 + c];
                float2 B1 = Bs2[(k0 + 4 + gc) * LDB2 + c];
                uint32_t bh0 = __float_as_uint(B0.x), bl0 = __float_as_uint(B0.y);
                uint32_t bh1 = __float_as_uint(B1.x), bl1 = __float_as_uint(B1.y);
                #pragma unroll
                for (int mf = 0; mf < 2; mf++) {
                    uint32_t ah0 = __float_as_uint(A[mf][0].x), al0 = __float_as_uint(A[mf][0].y);
                    uint32_t ah1 = __float_as_uint(A[mf][1].x), al1 = __float_as_uint(A[mf][1].y);
                    uint32_t ah2 = __float_as_uint(A[mf][2].x), al2 = __float_as_uint(A[mf][2].y);
                    uint32_t ah3 = __float_as_uint(A[mf][3].x), al3 = __float_as_uint(A[mf][3].y);
                    mma_tf32(acc[mf][nf], ah0, ah1, ah2, ah3, bh0, bh1);
                    mma_tf32(acc[mf][nf], ah0, ah1, ah2, ah3, bl0, bl1);
                    mma_tf32(acc[mf][nf], al0, al1, al2, al3, bh0, bh1);
                }
            }
        }
    }

    #pragma unroll
    for (int mf = 0; mf < 2; mf++) {
        int r0 = m0 + mbase + mf * 16 + gr;
        int r1 = r0 + 8;
        float n0 = (r0 < N_NODES) ? g_norm[r0] : 0.f;
        float n1 = (r1 < N_NODES) ? g_norm[r1] : 0.f;
        #pragma unroll
        for (int nf = 0; nf < 8; nf++) {
            int c = nbase + nf * 8 + gc * 2;
            if (r0 < N_NODES) {
                __half2 v = __floats2half2_rn(acc[mf][nf].x * n0, acc[mf][nf].y * n0);
                *reinterpret_cast<__half2*>(g_yh + (size_t)r0 * HID + c) = v;
            }
            if (r1 < N_NODES) {
                __half2 v = __floats2half2_rn(acc[mf][nf].z * n1, acc[mf][nf].w * n1);
                *reinterpret_cast<__half2*>(g_yh + (size_t)r1 * HID + c) = v;
            }
        }
    }
}

// ---------------- layers 1-3 GEMM: y = (h_fp16 @ W) * norm -> fp16 ----------------
// A is fp16 -> exact in tf32: NO A split, 2-pass MMA (a*bhi + a*blo).
// A smem is plain float [128][LDAF] (100 KB total -> 2 CTAs/SM).
__global__ __launch_bounds__(256, 2) void gemm_f16a_kernel(const float* __restrict__ W) {
    extern __shared__ float smf[];
    float* As = smf;                                  // [128][LDAF]
    float2* Bs2 = reinterpret_cast<float2*>(smf + 128 * LDAF);  // [KC][LDB2]
    int tid = threadIdx.x;
    int m0 = blockIdx.x * 128;
    int lane = tid & 31, wid = tid >> 5;
    int warpM = wid >> 1, warpN = wid & 1;
    int mbase = warpM * 32, nbase = warpN * 64;
    int gr = lane >> 2, gc = lane & 3;

    float4 acc[2][8];
    #pragma unroll
    for (int mf = 0; mf < 2; mf++)
        #pragma unroll
        for (int nf = 0; nf < 8; nf++)
            acc[mf][nf] = make_float4(0.f, 0.f, 0.f, 0.f);

    #pragma unroll
    for (int kc = 0; kc < 2; kc++) {
        int k0c = kc * KC;
        if (kc) __syncthreads();
        // stage A chunk: 128 rows x 64 halves -> 1024 uint4 (8 halves each)
        #pragma unroll
        for (int i = 0; i < 4; i++) {
            int idx = tid + i * 256;
            int row = idx >> 3;
            int h8 = (idx & 7) << 3;
            float f[8];
            if (m0 + row < N_NODES) {
                uint4 raw = *reinterpret_cast<const uint4*>(
                    g_hh + (size_t)(m0 + row) * HID + k0c + h8);
                float2 p0 = __half22float2(*reinterpret_cast<const __half2*>(&raw.x));
                float2 p1 = __half22float2(*reinterpret_cast<const __half2*>(&raw.y));
                float2 p2 = __half22float2(*reinterpret_cast<const __half2*>(&raw.z));
                float2 p3 = __half22float2(*reinterpret_cast<const __half2*>(&raw.w));
                f[0] = p0.x; f[1] = p0.y; f[2] = p1.x; f[3] = p1.y;
                f[4] = p2.x; f[5] = p2.y; f[6] = p3.x; f[7] = p3.y;
            } else {
                #pragma unroll
                for (int j = 0; j < 8; j++) f[j] = 0.f;
            }
            float* p = As + row * LDAF + h8;
            #pragma unroll
            for (int j = 0; j < 8; j++) p[j] = f[j];
        }
        // stage B chunk: 64 k-rows x 128 n-cols, split hi/lo
        #pragma unroll
        for (int i = 0; i < 8; i++) {
            int idx = tid + i * 256;
            int kr = idx >> 5;
            int c4 = (idx & 31) << 2;
            float4 v = *reinterpret_cast<const float4*>(W + (size_t)(k0c + kr) * HID + c4);
            float2* p = Bs2 + kr * LDB2 + c4;
            p[0] = split_tf32(v.x); p[1] = split_tf32(v.y);
            p[2] = split_tf32(v.z); p[3] = split_tf32(v.w);
        }
        __syncthreads();

        #pragma unroll
        for (int ks = 0; ks < 8; ks++) {
            int k0 = ks * 8;
            uint32_t ah[2][4];
            #pragma unroll
            for (int mf = 0; mf < 2; mf++) {
                int r = mbase + mf * 16 + gr;
                ah[mf][0] = __float_as_uint(As[r * LDAF + k0 + gc]);
                ah[mf][1] = __float_as_uint(As[(r + 8) * LDAF + k0 + gc]);
                ah[mf][2] = __float_as_uint(As[r * LDAF + k0 + gc + 4]);
                ah[mf][3] = __float_as_uint(As[(r + 8) * LDAF + k0 + gc + 4]);
            }
            #pragma unroll
            for (int nf = 0; nf < 8; nf++) {
                int c = nbase + nf * 8 + gr;
                float2 B0 = Bs2[(k0 + gc) * LDB2 + c];
                float2 B1 = Bs2[(k0 + 4 + gc) * LDB2 + c];
                uint32_t bh0 = __float_as_uint(B0.x), bl0 = __float_as_uint(B0.y);
                uint32_t bh1 = __float_as_uint(B1.x), bl1 = __float_as_uint(B1.y);
                #pragma unroll
                for (int mf = 0; mf < 2; mf++) {
                    mma_tf32(acc[mf][nf], ah[mf][0], ah[mf][1], ah[mf][2], ah[mf][3], bh0, bh1);
                    mma_tf32(acc[mf][nf], ah[mf][0], ah[mf][1], ah[mf][2], ah[mf][3], bl0, bl1);
                }
            }
        }
    }

    #pragma unroll
    for (int mf = 0; mf < 2; mf++) {
        int r0 = m0 + mbase + mf * 16 + gr;
        int r1 = r0 + 8;
        float n0 = (r0 < N_NODES) ? g_norm[r0] : 0.f;
        float n1 = (r1 < N_NODES) ? g_norm[r1] : 0.f;
        #pragma unroll
        for (int nf = 0; nf < 8; nf++) {
            int c = nbase + nf * 8 + gc * 2;
            if (r0 < N_NODES) {
                __half2 v = __floats2half2_rn(acc[mf][nf].x * n0, acc[mf][nf].y * n0);
                *reinterpret_cast<__half2*>(g_yh + (size_t)r0 * HID + c) = v;
            }
            if (r1 < N_NODES) {
                __half2 v = __floats2half2_rn(acc[mf][nf].z * n1, acc[mf][nf].w * n1);
                *reinterpret_cast<__half2*>(g_yh + (size_t)r1 * HID + c) = v;
            }
        }
    }
}

// ---------------- aggregation + BN(eval) + ReLU, warp per node, fp16 gather ----------------
// Writes fp16 h. last!=0: fuse global-mean-pool instead of writing h.
__global__ __launch_bounds__(256) void agg_kernel(const float* __restrict__ bs,
                                                  const float* __restrict__ gam,
                                                  const float* __restrict__ bet,
                                                  const float* __restrict__ mean,
                                                  const float* __restrict__ var,
                                                  const int* __restrict__ batch,
                                                  int last) {
    int wid = threadIdx.x >> 5, lane = threadIdx.x & 31;
    int n = blockIdx.x * 8 + wid;
    if (n >= N_NODES) return;
    const uint2* __restrict__ y2 = reinterpret_cast<const uint2*>(g_yh);

    uint2 sraw = y2[(size_t)n * 32 + lane];      // self term: norm*y[n]
    float2 s0 = __half22float2(*reinterpret_cast<const __half2*>(&sraw.x));
    float2 s1 = __half22float2(*reinterpret_cast<const __half2*>(&sraw.y));
    float4 acc = make_float4(s0.x, s0.y, s1.x, s1.y);

    int e = g_rowptr[n], e1 = g_rowptr[n + 1];
    for (; e + 4 <= e1; e += 4) {
        int sA = g_srcs[e], sB = g_srcs[e + 1], sC = g_srcs[e + 2], sD = g_srcs[e + 3];
        uint2 rA = y2[(size_t)sA * 32 + lane];
        uint2 rB = y2[(size_t)sB * 32 + lane];
        uint2 rC = y2[(size_t)sC * 32 + lane];
        uint2 rD = y2[(size_t)sD * 32 + lane];
        float2 a0 = __half22float2(*reinterpret_cast<const __half2*>(&rA.x));
        float2 a1 = __half22float2(*reinterpret_cast<const __half2*>(&rA.y));
        float2 b0 = __half22float2(*reinterpret_cast<const __half2*>(&rB.x));
        float2 b1 = __half22float2(*reinterpret_cast<const __half2*>(&rB.y));
        float2 c0 = __half22float2(*reinterpret_cast<const __half2*>(&rC.x));
        float2 c1 = __half22float2(*reinterpret_cast<const __half2*>(&rC.y));
        float2 d0 = __half22float2(*reinterpret_cast<const __half2*>(&rD.x));
        float2 d1 = __half22float2(*reinterpret_cast<const __half2*>(&rD.y));
        acc.x += (a0.x + b0.x) + (c0.x + d0.x);
        acc.y += (a0.y + b0.y) + (c0.y + d0.y);
        acc.z += (a1.x + b1.x) + (c1.x + d1.x);
        acc.w += (a1.y + b1.y) + (c1.y + d1.y);
    }
    for (; e < e1; e++) {
        int s = g_srcs[e];
        uint2 raw = y2[(size_t)s * 32 + lane];
        float2 f0 = __half22float2(*reinterpret_cast<const __half2*>(&raw.x));
        float2 f1 = __half22float2(*reinterpret_cast<const __half2*>(&raw.y));
        acc.x += f0.x; acc.y += f0.y; acc.z += f1.x; acc.w += f1.y;
    }
    float nrm = g_norm[n];
    int j = lane * 4;
    float4 b4 = *reinterpret_cast<const float4*>(bs + j);
    float4 g4 = *reinterpret_cast<const float4*>(gam + j);
    float4 be4 = *reinterpret_cast<const float4*>(bet + j);
    float4 m4 = *reinterpret_cast<const float4*>(mean + j);
    float4 v4 = *reinterpret_cast<const float4*>(var + j);
    float4 r;
    r.x = fmaxf((nrm * acc.x + b4.x - m4.x) * (g4.x * rsqrtf(v4.x + BN_EPS)) + be4.x, 0.f);
    r.y = fmaxf((nrm * acc.y + b4.y - m4.y) * (g4.y * rsqrtf(v4.y + BN_EPS)) + be4.y, 0.f);
    r.z = fmaxf((nrm * acc.z + b4.z - m4.z) * (g4.z * rsqrtf(v4.z + BN_EPS)) + be4.z, 0.f);
    r.w = fmaxf((nrm * acc.w + b4.w - m4.w) * (g4.w * rsqrtf(v4.w + BN_EPS)) + be4.w, 0.f);
    if (!last) {
        uint2 packed;
        *reinterpret_cast<__half2*>(&packed.x) = __floats2half2_rn(r.x, r.y);
        *reinterpret_cast<__half2*>(&packed.y) = __floats2half2_rn(r.z, r.w);
        reinterpret_cast<uint2*>(g_hh)[(size_t)n * 32 + lane] = packed;
    } else {
        int b = batch[n];
        float* p = &g_pool[b * HID + lane * 4];
        atomicAdd(p, r.x); atomicAdd(p + 1, r.y);
        atomicAdd(p + 2, r.z); atomicAdd(p + 3, r.w);
        if (lane == 0) atomicAdd(&g_cnt[b], 1.0f);
    }
}

// ---------------- final projection: out[g] = pooled[g] @ W_out + b_out ----------------
__global__ __launch_bounds__(128) void out_kernel(const float* __restrict__ W_out,
                                                  const float* __restrict__ b_out,
                                                  float* __restrict__ out) {
    int g = blockIdx.x;
    int tid = threadIdx.x;
    int lane = tid & 31, wid = tid >> 5;
    float cnt = fmaxf(g_cnt[g], 1.0f);
    float p = g_pool[g * HID + tid] / cnt;
    float v[5];
    #pragma unroll
    for (int o = 0; o < 5; o++) v[o] = p * W_out[tid * 5 + o];
    #pragma unroll
    for (int o = 0; o < 5; o++)
        #pragma unroll
        for (int off = 16; off > 0; off >>= 1)
            v[o] += __shfl_down_sync(0xFFFFFFFFu, v[o], off);
    __shared__ float sred[4][5];
    if (lane == 0) {
        #pragma unroll
        for (int o = 0; o < 5; o++) sred[wid][o] = v[o];
    }
    __syncthreads();
    if (tid < 5) {
        float s = sred[0][tid] + sred[1][tid] + sred[2][tid] + sred[3][tid] + b_out[tid];
        out[g * 5 + tid] = s;
    }
}

// ---------------- launch ----------------
extern "C" void kernel_launch(void* const* d_in, const int* in_sizes, int n_in,
                              void* d_out, int out_size) {
    const float* x      = (const float*)d_in[0];
    const int*   edge   = (const int*)d_in[1];
    const int*   batch  = (const int*)d_in[2];
    const float* Ws     = (const float*)d_in[3];
    const float* bs     = (const float*)d_in[4];
    const float* gammas = (const float*)d_in[5];
    const float* betas  = (const float*)d_in[6];
    const float* rmean  = (const float*)d_in[7];
    const float* rvar   = (const float*)d_in[8];
    const float* W_out  = (const float*)d_in[9];
    const float* b_out  = (const float*)d_in[10];
    const int* src = edge;
    const int* dst = edge + N_EDGES;

    cudaFuncSetAttribute(gemm_l0_kernel,
                         cudaFuncAttributeMaxDynamicSharedMemorySize, GEMM_L0_SMEM);
    cudaFuncSetAttribute(gemm_f16a_kernel,
                         cudaFuncAttributeMaxDynamicSharedMemorySize, GEMM_F16_SMEM);

    init_kernel<<<256, 256>>>();
    count_kernel<<<(N_EDGES + 255) / 256, 256>>>(dst);
    scan_reduce_kernel<<<SCAN_NB, 256>>>();
    scan_partials_kernel<<<1, 32>>>();
    scan_final_kernel<<<SCAN_NB, 1024>>>();
    scatter_kernel<<<(N_EDGES + 255) / 256, 256>>>(src, dst);

    int gemm_blocks = (N_NODES + 127) / 128;
    int node_warp_blocks = (N_NODES + 7) / 8;
    for (int l = 0; l < 4; l++) {
        if (l == 0)
            gemm_l0_kernel<<<gemm_blocks, 256, GEMM_L0_SMEM>>>(x, Ws);
        else
            gemm_f16a_kernel<<<gemm_blocks, 256, GEMM_F16_SMEM>>>(Ws + (size_t)l * HID * HID);
        agg_kernel<<<node_warp_blocks, 256>>>(bs + l * HID, gammas + l * HID,
                                              betas + l * HID, rmean + l * HID,
                                              rvar + l * HID, batch,
                                              l == 3 ? 1 : 0);
    }
    out_kernel<<<N_GRAPHS, 128>>>(W_out, b_out, (float*)d_out);
}

// round 13
// speedup vs baseline: 1.6909x; 1.1979x over previous
#include <cuda_runtime.h>
#include <cuda_fp16.h>
#include <cstdint>

#define N_NODES 100000
#define N_EDGES 1600000
#define N_GRAPHS 2000
#define HID 128
#define BN_EPS 1e-5f

// ---------------- scratch (device globals; no allocation allowed) ----------------
__device__ __half g_yh[N_NODES * HID];    // y = (h @ W) * norm, fp16 (25.6 MB)
__device__ __half g_hh[N_NODES * HID];    // activations fp16        (25.6 MB)
__device__ float g_norm[N_NODES];
__device__ int   g_deg[N_NODES];
__device__ int   g_rowptr[N_NODES + 1];
__device__ int   g_cursor[N_NODES];
__device__ int   g_srcs[N_EDGES];         // CSR by dst (6.4 MB)
__device__ float g_pool[N_GRAPHS * HID];
__device__ float g_cnt[N_GRAPHS];

#define SCAN_BLK 4096
#define SCAN_NB ((N_NODES + SCAN_BLK - 1) / SCAN_BLK)   // 25
__device__ int g_bsum[SCAN_NB];

// ---------------- setup kernels ----------------
__global__ void init_kernel() {
    int i = blockIdx.x * blockDim.x + threadIdx.x;
    int stride = gridDim.x * blockDim.x;
    for (int t = i; t < N_GRAPHS * HID; t += stride) g_pool[t] = 0.f;
    for (int t = i; t < N_NODES; t += stride) g_deg[t] = 0;
    for (int t = i; t < N_GRAPHS; t += stride) g_cnt[t] = 0.f;
}

// x fp32 -> fp16 (feeds unified fp16 GEMM for layer 0)
__global__ __launch_bounds__(256) void convert_x_kernel(const float* __restrict__ x) {
    int t = blockIdx.x * blockDim.x + threadIdx.x;   // one task = 8 floats
    if (t >= N_NODES * HID / 8) return;
    const float4* xin = reinterpret_cast<const float4*>(x);
    float4 a = xin[t * 2], b = xin[t * 2 + 1];
    uint4 o;
    *reinterpret_cast<__half2*>(&o.x) = __floats2half2_rn(a.x, a.y);
    *reinterpret_cast<__half2*>(&o.y) = __floats2half2_rn(a.z, a.w);
    *reinterpret_cast<__half2*>(&o.z) = __floats2half2_rn(b.x, b.y);
    *reinterpret_cast<__half2*>(&o.w) = __floats2half2_rn(b.z, b.w);
    reinterpret_cast<uint4*>(g_hh)[t] = o;
}

__global__ void count_kernel(const int* __restrict__ dst) {
    int e = blockIdx.x * blockDim.x + threadIdx.x;
    if (e < N_EDGES) atomicAdd(&g_deg[dst[e]], 1);
}

// ---- 3-phase prefix scan over g_deg -> rowptr/cursor + norm ----
__global__ __launch_bounds__(256) void scan_reduce_kernel() {
    int b = blockIdx.x;
    int base = b * SCAN_BLK;
    int tid = threadIdx.x;
    int sum = 0;
    for (int i = tid; i < SCAN_BLK; i += 256) {
        int idx = base + i;
        if (idx < N_NODES) sum += g_deg[idx];
    }
    #pragma unroll
    for (int o = 16; o > 0; o >>= 1) sum += __shfl_down_sync(0xFFFFFFFFu, sum, o);
    __shared__ int ws[8];
    int lane = tid & 31, wid = tid >> 5;
    if (lane == 0) ws[wid] = sum;
    __syncthreads();
    if (tid == 0) {
        int t = 0;
        #pragma unroll
        for (int i = 0; i < 8; i++) t += ws[i];
        g_bsum[b] = t;
    }
}

__global__ void scan_partials_kernel() {
    int lane = threadIdx.x;
    int v = (lane < SCAN_NB) ? g_bsum[lane] : 0;
    int x = v;
    #pragma unroll
    for (int o = 1; o < 32; o <<= 1) {
        int t = __shfl_up_sync(0xFFFFFFFFu, x, o);
        if (lane >= o) x += t;
    }
    if (lane < SCAN_NB) g_bsum[lane] = x - v;   // exclusive
    if (lane == 31) g_rowptr[N_NODES] = x;
}

__global__ __launch_bounds__(1024) void scan_final_kernel() {
    int b = blockIdx.x;
    int base = b * SCAN_BLK;
    int tid = threadIdx.x;
    int lane = tid & 31, wid = tid >> 5;
    int i0 = base + tid * 4;
    int v0 = 0, v1 = 0, v2 = 0, v3 = 0;
    if (i0 + 3 < N_NODES) {
        int4 v = *reinterpret_cast<const int4*>(&g_deg[i0]);
        v0 = v.x; v1 = v.y; v2 = v.z; v3 = v.w;
    } else {
        if (i0 < N_NODES) v0 = g_deg[i0];
        if (i0 + 1 < N_NODES) v1 = g_deg[i0 + 1];
        if (i0 + 2 < N_NODES) v2 = g_deg[i0 + 2];
        if (i0 + 3 < N_NODES) v3 = g_deg[i0 + 3];
    }
    int t0 = v0, t1 = t0 + v1, t2 = t1 + v2, t3 = t2 + v3;
    int ts = t3;
    int ws_i = ts;
    #pragma unroll
    for (int o = 1; o < 32; o <<= 1) {
        int t = __shfl_up_sync(0xFFFFFFFFu, ws_i, o);
        if (lane >= o) ws_i += t;
    }
    __shared__ int wsum[32];
    if (lane == 31) wsum[wid] = ws_i;
    __syncthreads();
    if (wid == 0) {
        int w = wsum[lane];
        #pragma unroll
        for (int o = 1; o < 32; o <<= 1) {
            int t = __shfl_up_sync(0xFFFFFFFFu, w, o);
            if (lane >= o) w += t;
        }
        wsum[lane] = w;
    }
    __syncthreads();
    int excl = g_bsum[b] + (ws_i - ts) + ((wid > 0) ? wsum[wid - 1] : 0);
    int e0 = excl, e1 = excl + t0, e2 = excl + t1, e3 = excl + t2;
    if (i0 < N_NODES)     { g_rowptr[i0] = e0;   g_cursor[i0] = e0;   g_norm[i0] = rsqrtf((float)v0 + 1.f); }
    if (i0 + 1 < N_NODES) { g_rowptr[i0+1] = e1; g_cursor[i0+1] = e1; g_norm[i0+1] = rsqrtf((float)v1 + 1.f); }
    if (i0 + 2 < N_NODES) { g_rowptr[i0+2] = e2; g_cursor[i0+2] = e2; g_norm[i0+2] = rsqrtf((float)v2 + 1.f); }
    if (i0 + 3 < N_NODES) { g_rowptr[i0+3] = e3; g_cursor[i0+3] = e3; g_norm[i0+3] = rsqrtf((float)v3 + 1.f); }
}

__global__ void scatter_kernel(const int* __restrict__ src, const int* __restrict__ dst) {
    int e = blockIdx.x * blockDim.x + threadIdx.x;
    if (e < N_EDGES) {
        int d = dst[e];
        int pos = atomicAdd(&g_cursor[d], 1);
        g_srcs[pos] = src[e];
    }
}

// ---------------- fp16 tensor-core GEMM: y = (h_fp16 @ W) * norm -> fp16 ----------------
// A fp16 exact. W split into fp16 hi + fp16 lo (residual ~2^-22): 2-pass
// HMMA m16n8k16 with fp32 accumulate. Smem holds pre-packed fragments:
//   A2[row][kblk*4+j]  = uint2( half2@kpair(kblk*8+j), half2@kpair(kblk*8+j+4) )
//   B2[kpair][n]       = uint2( hi half2(k,k+1), lo half2(k,k+1) )
// Pitches 36/132 uint2 (both ==4 mod 16) -> all LDS.64 bank-pair bijective.
#define LDA2U 36
#define LDB2U 132
#define GEMM_F16_SMEM ((128 * LDA2U + 64 * LDB2U) * 8)

__device__ __forceinline__ void mma_f16(float4& d, uint32_t a0, uint32_t a1,
                                        uint32_t a2, uint32_t a3,
                                        uint32_t b0, uint32_t b1) {
    asm volatile(
        "mma.sync.aligned.m16n8k16.row.col.f32.f16.f16.f32 "
        "{%0,%1,%2,%3}, {%4,%5,%6,%7}, {%8,%9}, {%0,%1,%2,%3};"
        : "+f"(d.x), "+f"(d.y), "+f"(d.z), "+f"(d.w)
        : "r"(a0), "r"(a1), "r"(a2), "r"(a3), "r"(b0), "r"(b1));
}

__global__ __launch_bounds__(256, 2) void gemm_f16_kernel(const float* __restrict__ W) {
    extern __shared__ uint2 smu[];
    uint2* A2 = smu;                    // [128][LDA2U]
    uint2* B2 = smu + 128 * LDA2U;      // [64][LDB2U]
    int tid = threadIdx.x;
    int m0 = blockIdx.x * 128;
    int lane = tid & 31, wid = tid >> 5;
    int warpM = wid >> 1, warpN = wid & 1;
    int mbase = warpM * 32, nbase = warpN * 64;
    int gr = lane >> 2, gc = lane & 3;

    // ---- stage A: 128 rows x 8 kblks, pack (j, j+4) kpair interleave ----
    #pragma unroll
    for (int i = 0; i < 4; i++) {
        int t = tid + i * 256;
        int row = t >> 3, kblk = t & 7;
        uint4 q0 = make_uint4(0, 0, 0, 0), q1 = make_uint4(0, 0, 0, 0);
        if (m0 + row < N_NODES) {
            const uint4* hr = reinterpret_cast<const uint4*>(g_hh + (size_t)(m0 + row) * HID);
            q0 = hr[kblk * 2];
            q1 = hr[kblk * 2 + 1];
        }
        uint2* p = A2 + row * LDA2U + kblk * 4;
        p[0] = make_uint2(q0.x, q1.x);
        p[1] = make_uint2(q0.y, q1.y);
        p[2] = make_uint2(q0.z, q1.z);
        p[3] = make_uint2(q0.w, q1.w);
    }
    // ---- stage B: 64 kpairs x 128 cols, split W into fp16 (hi, lo) ----
    #pragma unroll
    for (int i = 0; i < 8; i++) {
        int t = tid + i * 256;
        int kp = t >> 5;
        int c = (t & 31) << 2;
        float4 va = *reinterpret_cast<const float4*>(W + (size_t)(2 * kp) * HID + c);
        float4 vb = *reinterpret_cast<const float4*>(W + (size_t)(2 * kp + 1) * HID + c);
        uint2* p = B2 + kp * LDB2U + c;
        const float* fa = &va.x;
        const float* fb = &vb.x;
        #pragma unroll
        for (int j = 0; j < 4; j++) {
            __half ha = __float2half_rn(fa[j]);
            __half hb = __float2half_rn(fb[j]);
            __half la = __float2half_rn(fa[j] - __half2float(ha));
            __half lb = __float2half_rn(fb[j] - __half2float(hb));
            uint2 o;
            *reinterpret_cast<__half2*>(&o.x) = __halves2half2(ha, hb);
            *reinterpret_cast<__half2*>(&o.y) = __halves2half2(la, lb);
            p[j] = o;
        }
    }
    __syncthreads();

    float4 acc[2][8];
    #pragma unroll
    for (int mf = 0; mf < 2; mf++)
        #pragma unroll
        for (int nf = 0; nf < 8; nf++)
            acc[mf][nf] = make_float4(0.f, 0.f, 0.f, 0.f);

    #pragma unroll
    for (int kblk = 0; kblk < 8; kblk++) {
        uint2 Aa[2], Ab[2];
        #pragma unroll
        for (int mf = 0; mf < 2; mf++) {
            int r = mbase + mf * 16 + gr;
            Aa[mf] = A2[r * LDA2U + kblk * 4 + gc];        // (a0, a2)
            Ab[mf] = A2[(r + 8) * LDA2U + kblk * 4 + gc];  // (a1, a3)
        }
        #pragma unroll
        for (int nf = 0; nf < 8; nf++) {
            int n = nbase + nf * 8 + gr;
            uint2 b0 = B2[(kblk * 8 + gc) * LDB2U + n];        // (b0hi, b0lo)
            uint2 b1 = B2[(kblk * 8 + gc + 4) * LDB2U + n];    // (b1hi, b1lo)
            #pragma unroll
            for (int mf = 0; mf < 2; mf++) {
                mma_f16(acc[mf][nf], Aa[mf].x, Ab[mf].x, Aa[mf].y, Ab[mf].y, b0.x, b1.x);
                mma_f16(acc[mf][nf], Aa[mf].x, Ab[mf].x, Aa[mf].y, Ab[mf].y, b0.y, b1.y);
            }
        }
    }

    // epilogue: y = acc * norm[row], stored fp16
    #pragma unroll
    for (int mf = 0; mf < 2; mf++) {
        int r0 = m0 + mbase + mf * 16 + gr;
        int r1 = r0 + 8;
        float n0 = (r0 < N_NODES) ? g_norm[r0] : 0.f;
        float n1 = (r1 < N_NODES) ? g_norm[r1] : 0.f;
        #pragma unroll
        for (int nf = 0; nf < 8; nf++) {
            int c = nbase + nf * 8 + gc * 2;
            if (r0 < N_NODES) {
                __half2 v = __floats2half2_rn(acc[mf][nf].x * n0, acc[mf][nf].y * n0);
                *reinterpret_cast<__half2*>(g_yh + (size_t)r0 * HID + c) = v;
            }
            if (r1 < N_NODES) {
                __half2 v = __floats2half2_rn(acc[mf][nf].z * n1, acc[mf][nf].w * n1);
                *reinterpret_cast<__half2*>(g_yh + (size_t)r1 * HID + c) = v;
            }
        }
    }
}

// ---------------- aggregation + BN(eval) + ReLU, HALF-warp per node ----------------
// 16 lanes x uint4 (8 halves) per node row; 2 independent chains per warp.
// last!=0: fuse global-mean-pool instead of writing h.
__global__ __launch_bounds__(256) void agg_kernel(const float* __restrict__ bs,
                                                  const float* __restrict__ gam,
                                                  const float* __restrict__ bet,
                                                  const float* __restrict__ mean,
                                                  const float* __restrict__ var,
                                                  const int* __restrict__ batch,
                                                  int last) {
    int hw = threadIdx.x >> 4;          // half-warp id in block (0..15)
    int l16 = threadIdx.x & 15;         // lane within half-warp
    int n = blockIdx.x * 16 + hw;
    if (n >= N_NODES) return;
    const uint4* __restrict__ y4 = reinterpret_cast<const uint4*>(g_yh);

    float a0, a1, a2, a3, a4, a5, a6, a7;
    {
        uint4 sr = y4[(size_t)n * 16 + l16];   // self term: norm*y[n]
        float2 p0 = __half22float2(*reinterpret_cast<const __half2*>(&sr.x));
        float2 p1 = __half22float2(*reinterpret_cast<const __half2*>(&sr.y));
        float2 p2 = __half22float2(*reinterpret_cast<const __half2*>(&sr.z));
        float2 p3 = __half22float2(*reinterpret_cast<const __half2*>(&sr.w));
        a0 = p0.x; a1 = p0.y; a2 = p1.x; a3 = p1.y;
        a4 = p2.x; a5 = p2.y; a6 = p3.x; a7 = p3.y;
    }

    int e = g_rowptr[n], e1 = g_rowptr[n + 1];
    for (; e + 4 <= e1; e += 4) {
        int sA = g_srcs[e], sB = g_srcs[e + 1], sC = g_srcs[e + 2], sD = g_srcs[e + 3];
        uint4 rA = y4[(size_t)sA * 16 + l16];
        uint4 rB = y4[(size_t)sB * 16 + l16];
        uint4 rC = y4[(size_t)sC * 16 + l16];
        uint4 rD = y4[(size_t)sD * 16 + l16];
        #pragma unroll
        for (int q = 0; q < 1; q++) {}  // keep loads batched above
        float2 t;
        t = __half22float2(*reinterpret_cast<const __half2*>(&rA.x)); a0 += t.x; a1 += t.y;
        t = __half22float2(*reinterpret_cast<const __half2*>(&rA.y)); a2 += t.x; a3 += t.y;
        t = __half22float2(*reinterpret_cast<const __half2*>(&rA.z)); a4 += t.x; a5 += t.y;
        t = __half22float2(*reinterpret_cast<const __half2*>(&rA.w)); a6 += t.x; a7 += t.y;
        t = __half22float2(*reinterpret_cast<const __half2*>(&rB.x)); a0 += t.x; a1 += t.y;
        t = __half22float2(*reinterpret_cast<const __half2*>(&rB.y)); a2 += t.x; a3 += t.y;
        t = __half22float2(*reinterpret_cast<const __half2*>(&rB.z)); a4 += t.x; a5 += t.y;
        t = __half22float2(*reinterpret_cast<const __half2*>(&rB.w)); a6 += t.x; a7 += t.y;
        t = __half22float2(*reinterpret_cast<const __half2*>(&rC.x)); a0 += t.x; a1 += t.y;
        t = __half22float2(*reinterpret_cast<const __half2*>(&rC.y)); a2 += t.x; a3 += t.y;
        t = __half22float2(*reinterpret_cast<const __half2*>(&rC.z)); a4 += t.x; a5 += t.y;
        t = __half22float2(*reinterpret_cast<const __half2*>(&rC.w)); a6 += t.x; a7 += t.y;
        t = __half22float2(*reinterpret_cast<const __half2*>(&rD.x)); a0 += t.x; a1 += t.y;
        t = __half22float2(*reinterpret_cast<const __half2*>(&rD.y)); a2 += t.x; a3 += t.y;
        t = __half22float2(*reinterpret_cast<const __half2*>(&rD.z)); a4 += t.x; a5 += t.y;
        t = __half22float2(*reinterpret_cast<const __half2*>(&rD.w)); a6 += t.x; a7 += t.y;
    }
    for (; e < e1; e++) {
        int s = g_srcs[e];
        uint4 r = y4[(size_t)s * 16 + l16];
        float2 t;
        t = __half22float2(*reinterpret_cast<const __half2*>(&r.x)); a0 += t.x; a1 += t.y;
        t = __half22float2(*reinterpret_cast<const __half2*>(&r.y)); a2 += t.x; a3 += t.y;
        t = __half22float2(*reinterpret_cast<const __half2*>(&r.z)); a4 += t.x; a5 += t.y;
        t = __half22float2(*reinterpret_cast<const __half2*>(&r.w)); a6 += t.x; a7 += t.y;
    }

    float nrm = g_norm[n];
    int j = l16 * 8;
    float4 bA = *reinterpret_cast<const float4*>(bs + j);
    float4 bB = *reinterpret_cast<const float4*>(bs + j + 4);
    float4 gA = *reinterpret_cast<const float4*>(gam + j);
    float4 gB = *reinterpret_cast<const float4*>(gam + j + 4);
    float4 eA = *reinterpret_cast<const float4*>(bet + j);
    float4 eB = *reinterpret_cast<const float4*>(bet + j + 4);
    float4 mA = *reinterpret_cast<const float4*>(mean + j);
    float4 mB = *reinterpret_cast<const float4*>(mean + j + 4);
    float4 vA = *reinterpret_cast<const float4*>(var + j);
    float4 vB = *reinterpret_cast<const float4*>(var + j + 4);
    float r0 = fmaxf((nrm * a0 + bA.x - mA.x) * (gA.x * rsqrtf(vA.x + BN_EPS)) + eA.x, 0.f);
    float r1 = fmaxf((nrm * a1 + bA.y - mA.y) * (gA.y * rsqrtf(vA.y + BN_EPS)) + eA.y, 0.f);
    float r2 = fmaxf((nrm * a2 + bA.z - mA.z) * (gA.z * rsqrtf(vA.z + BN_EPS)) + eA.z, 0.f);
    float r3 = fmaxf((nrm * a3 + bA.w - mA.w) * (gA.w * rsqrtf(vA.w + BN_EPS)) + eA.w, 0.f);
    float r4 = fmaxf((nrm * a4 + bB.x - mB.x) * (gB.x * rsqrtf(vB.x + BN_EPS)) + eB.x, 0.f);
    float r5 = fmaxf((nrm * a5 + bB.y - mB.y) * (gB.y * rsqrtf(vB.y + BN_EPS)) + eB.y, 0.f);
    float r6 = fmaxf((nrm * a6 + bB.z - mB.z) * (gB.z * rsqrtf(vB.z + BN_EPS)) + eB.z, 0.f);
    float r7 = fmaxf((nrm * a7 + bB.w - mB.w) * (gB.w * rsqrtf(vB.w + BN_EPS)) + eB.w, 0.f);

    if (!last) {
        uint4 packed;
        *reinterpret_cast<__half2*>(&packed.x) = __floats2half2_rn(r0, r1);
        *reinterpret_cast<__half2*>(&packed.y) = __floats2half2_rn(r2, r3);
        *reinterpret_cast<__half2*>(&packed.z) = __floats2half2_rn(r4, r5);
        *reinterpret_cast<__half2*>(&packed.w) = __floats2half2_rn(r6, r7);
        reinterpret_cast<uint4*>(g_hh)[(size_t)n * 16 + l16] = packed;
    } else {
        int b = batch[n];
        float* p = &g_pool[b * HID + j];
        atomicAdd(p, r0);     atomicAdd(p + 1, r1);
        atomicAdd(p + 2, r2); atomicAdd(p + 3, r3);
        atomicAdd(p + 4, r4); atomicAdd(p + 5, r5);
        atomicAdd(p + 6, r6); atomicAdd(p + 7, r7);
        if (l16 == 0) atomicAdd(&g_cnt[b], 1.0f);
    }
}

// ---------------- final projection: out[g] = pooled[g] @ W_out + b_out ----------------
__global__ __launch_bounds__(128) void out_kernel(const float* __restrict__ W_out,
                                                  const float* __restrict__ b_out,
                                                  float* __restrict__ out) {
    int g = blockIdx.x;
    int tid = threadIdx.x;
    int lane = tid & 31, wid = tid >> 5;
    float cnt = fmaxf(g_cnt[g], 1.0f);
    float p = g_pool[g * HID + tid] / cnt;
    float v[5];
    #pragma unroll
    for (int o = 0; o < 5; o++) v[o] = p * W_out[tid * 5 + o];
    #pragma unroll
    for (int o = 0; o < 5; o++)
        #pragma unroll
        for (int off = 16; off > 0; off >>= 1)
            v[o] += __shfl_down_sync(0xFFFFFFFFu, v[o], off);
    __shared__ float sred[4][5];
    if (lane == 0) {
        #pragma unroll
        for (int o = 0; o < 5; o++) sred[wid][o] = v[o];
    }
    __syncthreads();
    if (tid < 5) {
        float s = sred[0][tid] + sred[1][tid] + sred[2][tid] + sred[3][tid] + b_out[tid];
        out[g * 5 + tid] = s;
    }
}

// ---------------- launch ----------------
extern "C" void kernel_launch(void* const* d_in, const int* in_sizes, int n_in,
                              void* d_out, int out_size) {
    const float* x      = (const float*)d_in[0];
    const int*   edge   = (const int*)d_in[1];
    const int*   batch  = (const int*)d_in[2];
    const float* Ws     = (const float*)d_in[3];
    const float* bs     = (const float*)d_in[4];
    const float* gammas = (const float*)d_in[5];
    const float* betas  = (const float*)d_in[6];
    const float* rmean  = (const float*)d_in[7];
    const float* rvar   = (const float*)d_in[8];
    const float* W_out  = (const float*)d_in[9];
    const float* b_out  = (const float*)d_in[10];
    const int* src = edge;
    const int* dst = edge + N_EDGES;

    cudaFuncSetAttribute(gemm_f16_kernel,
                         cudaFuncAttributeMaxDynamicSharedMemorySize, GEMM_F16_SMEM);

    init_kernel<<<256, 256>>>();
    convert_x_kernel<<<(N_NODES * HID / 8 + 255) / 256, 256>>>(x);
    count_kernel<<<(N_EDGES + 255) / 256, 256>>>(dst);
    scan_reduce_kernel<<<SCAN_NB, 256>>>();
    scan_partials_kernel<<<1, 32>>>();
    scan_final_kernel<<<SCAN_NB, 1024>>>();
    scatter_kernel<<<(N_EDGES + 255) / 256, 256>>>(src, dst);

    int gemm_blocks = (N_NODES + 127) / 128;
    int agg_blocks = (N_NODES + 15) / 16;
    for (int l = 0; l < 4; l++) {
        gemm_f16_kernel<<<gemm_blocks, 256, GEMM_F16_SMEM>>>(Ws + (size_t)l * HID * HID);
        agg_kernel<<<agg_blocks, 256>>>(bs + l * HID, gammas + l * HID,
                                        betas + l * HID, rmean + l * HID,
                                        rvar + l * HID, batch,
                                        l == 3 ? 1 : 0);
    }
    out_kernel<<<N_GRAPHS, 128>>>(W_out, b_out, (float*)d_out);
}